// round 1
// baseline (speedup 1.0000x reference)
#include <cuda_runtime.h>
#include <cstdint>

// GCN: out2 = GCNagg(relu(GCNagg(x@W1) + b1) @ W2) + b2
// GCNagg(h)[r] = sum_{edges (r,c)} h[c]*dinv[r]*dinv[c]  (+ self loop r==c)
// deg = in-degree(+1 self loop), dinv = rsqrt(deg)

#define N_NODES 50000
#define F_IN    256
#define F_HID   256
#define F_OUT   128

// -------- scratch (device globals; no allocations allowed) --------
__device__ float g_h1  [(size_t)N_NODES * F_HID];  // x @ W1
__device__ float g_agg1[(size_t)N_NODES * F_HID];  // layer-1 aggregation
__device__ float g_h2  [(size_t)N_NODES * F_OUT];  // relu(agg1+b1) @ W2
__device__ float g_deg [N_NODES];
__device__ float g_dinv[N_NODES];
__device__ int   g_is64;                           // edge_index dtype flag

// -------- edge dtype detection (int32 vs int64, decided on-device) --------
__global__ void detect_dtype_kernel(const unsigned int* __restrict__ w, int nwords) {
    __shared__ unsigned int s_or;
    if (threadIdx.x == 0) s_or = 0u;
    __syncthreads();
    unsigned int v = 0u;
    // If data is int64 (values < 2^31, non-negative), every odd 32-bit word is 0.
    for (int i = 2 * threadIdx.x + 1; i < nwords; i += 2 * blockDim.x) v |= w[i];
    atomicOr(&s_or, v);
    __syncthreads();
    if (threadIdx.x == 0) g_is64 = (s_or == 0u) ? 1 : 0;
}

__device__ __forceinline__ long long edge_get(const void* p, long long i) {
    return g_is64 ? ((const long long*)p)[i] : (long long)((const int*)p)[i];
}

// -------- degree / norm --------
__global__ void init_deg_kernel(int n) {
    int i = blockIdx.x * blockDim.x + threadIdx.x;
    if (i < n) g_deg[i] = 1.0f;  // self loop
}

__global__ void deg_accum_kernel(const void* __restrict__ edges, int E) {
    int e = blockIdx.x * blockDim.x + threadIdx.x;
    if (e < E) {
        long long r = edge_get(edges, e);  // destination
        atomicAdd(&g_deg[r], 1.0f);
    }
}

__global__ void dinv_kernel(int n) {
    int i = blockIdx.x * blockDim.x + threadIdx.x;
    if (i < n) g_dinv[i] = rsqrtf(g_deg[i]);
}

// -------- fp32 GEMM: C[M,N] = op(A)[M,K] @ B[K,N] --------
// BM=BN=128, BK=8, 256 threads, 8x8 micro-tile per thread.
// RELU_BIAS: A element becomes relu(a + abias[k]) (fused layer-1 epilogue).
template <bool RELU_BIAS>
__global__ void sgemm128_kernel(const float* __restrict__ A,
                                const float* __restrict__ B,
                                const float* __restrict__ abias,
                                float* __restrict__ C,
                                int M, int N, int K) {
    __shared__ float As[8][132];   // [k][row], padded vs bank conflicts
    __shared__ float Bs[8][128];   // [k][col]

    const int tid = threadIdx.x;
    const int rowBase = blockIdx.y * 128;
    const int colBase = blockIdx.x * 128;

    // A tile load mapping: 128x8 floats, one float4 (4 k's) per thread
    const int arow = tid >> 1;          // 0..127
    const int ak   = (tid & 1) * 4;     // 0 or 4
    // B tile load mapping: 8x128 floats, one float4 per thread
    const int brow = tid >> 5;          // 0..7  (k)
    const int bcol = (tid & 31) * 4;    // 0..124

    const int ty = tid >> 4;            // 0..15 (row group)
    const int tx = tid & 15;            // 0..15 (col group)

    float acc[8][8];
    #pragma unroll
    for (int m = 0; m < 8; m++)
        #pragma unroll
        for (int n = 0; n < 8; n++) acc[m][n] = 0.0f;

    float ra[8], rb[8];

    for (int k0 = 0; k0 < K; k0 += 8) {
        // ---- load A tile (transposed into As[k][row]) ----
        const int gr = rowBase + arow;
        float4 av = make_float4(0.f, 0.f, 0.f, 0.f);
        if (gr < M)
            av = *reinterpret_cast<const float4*>(A + (long long)gr * K + k0 + ak);
        if (RELU_BIAS) {
            const float4 bv = *reinterpret_cast<const float4*>(abias + k0 + ak);
            av.x = fmaxf(av.x + bv.x, 0.f);
            av.y = fmaxf(av.y + bv.y, 0.f);
            av.z = fmaxf(av.z + bv.z, 0.f);
            av.w = fmaxf(av.w + bv.w, 0.f);
        }
        As[ak + 0][arow] = av.x;
        As[ak + 1][arow] = av.y;
        As[ak + 2][arow] = av.z;
        As[ak + 3][arow] = av.w;

        // ---- load B tile ----
        *reinterpret_cast<float4*>(&Bs[brow][bcol]) =
            *reinterpret_cast<const float4*>(B + (long long)(k0 + brow) * N + colBase + bcol);

        __syncthreads();

        #pragma unroll
        for (int k = 0; k < 8; k++) {
            #pragma unroll
            for (int m = 0; m < 8; m += 4)
                *reinterpret_cast<float4*>(&ra[m]) =
                    *reinterpret_cast<const float4*>(&As[k][ty * 8 + m]);
            #pragma unroll
            for (int n = 0; n < 8; n += 4)
                *reinterpret_cast<float4*>(&rb[n]) =
                    *reinterpret_cast<const float4*>(&Bs[k][tx * 8 + n]);
            #pragma unroll
            for (int m = 0; m < 8; m++)
                #pragma unroll
                for (int n = 0; n < 8; n++)
                    acc[m][n] = fmaf(ra[m], rb[n], acc[m][n]);
        }
        __syncthreads();
    }

    // ---- store ----
    #pragma unroll
    for (int m = 0; m < 8; m++) {
        const int gr = rowBase + ty * 8 + m;
        if (gr < M) {
            #pragma unroll
            for (int n = 0; n < 8; n += 4) {
                float4 v = make_float4(acc[m][n], acc[m][n + 1], acc[m][n + 2], acc[m][n + 3]);
                *reinterpret_cast<float4*>(C + (long long)gr * N + colBase + tx * 8 + n) = v;
            }
        }
    }
}

// -------- self-loop init: dst[i,f] = h[i,f]*dinv[i]^2 (+ bias[f]) --------
template <bool ADD_BIAS>
__global__ void self_init_kernel(const float* __restrict__ h,
                                 const float* __restrict__ bias,
                                 float* __restrict__ dst,
                                 int M, int F) {
    long long idx = (long long)blockIdx.x * blockDim.x + threadIdx.x;
    if (idx >= (long long)M * F) return;
    int node = (int)(idx / F);
    int f    = (int)(idx - (long long)node * F);
    float d = g_dinv[node];
    float v = h[idx] * d * d;
    if (ADD_BIAS) v += bias[f];
    dst[idx] = v;
}

// -------- edge scatter: agg[r,:] += h[c,:] * dinv[r]*dinv[c] --------
// One warp per edge; lanes stride float4s over the feature dim.
__global__ void scatter_kernel(const void* __restrict__ edges,
                               const float* __restrict__ h,
                               float* __restrict__ agg,
                               int E, int F) {
    const int warp = (blockIdx.x * blockDim.x + threadIdx.x) >> 5;
    const int lane = threadIdx.x & 31;
    if (warp >= E) return;
    const long long r = edge_get(edges, warp);       // destination
    const long long c = edge_get(edges, (long long)E + warp);  // source
    const float norm = g_dinv[r] * g_dinv[c];
    const float4* __restrict__ src = reinterpret_cast<const float4*>(h + c * F);
    float* __restrict__ dst = agg + r * F;
    const int nf4 = F >> 2;
    for (int i = lane; i < nf4; i += 32) {
        const float4 v = __ldg(&src[i]);
        const int f = i * 4;
        atomicAdd(&dst[f + 0], v.x * norm);
        atomicAdd(&dst[f + 1], v.y * norm);
        atomicAdd(&dst[f + 2], v.z * norm);
        atomicAdd(&dst[f + 3], v.w * norm);
    }
}

// ---------------------------------------------------------------
extern "C" void kernel_launch(void* const* d_in, const int* in_sizes, int n_in,
                              void* d_out, int out_size) {
    const float* x     = (const float*)d_in[0];
    const void*  edges = d_in[1];
    const float* W1    = (const float*)d_in[2];
    const float* b1    = (const float*)d_in[3];
    const float* W2    = (const float*)d_in[4];
    const float* b2    = (const float*)d_in[5];
    float* out = (float*)d_out;

    const int M = in_sizes[0] / F_IN;        // 50000
    const int E = in_sizes[1] / 2;           // 320000

    float* h1   = nullptr;  cudaGetSymbolAddress((void**)&h1,   g_h1);
    float* agg1 = nullptr;  cudaGetSymbolAddress((void**)&agg1, g_agg1);
    float* h2   = nullptr;  cudaGetSymbolAddress((void**)&h2,   g_h2);

    // 0) edge dtype detection (deterministic, graph-capturable)
    {
        int nwords = 2 * E;
        if (nwords > 4096) nwords = 4096;
        detect_dtype_kernel<<<1, 256>>>((const unsigned int*)edges, nwords);
    }

    // 1) degrees + dinv
    init_deg_kernel<<<(M + 255) / 256, 256>>>(M);
    deg_accum_kernel<<<(E + 255) / 256, 256>>>(edges, E);
    dinv_kernel<<<(M + 255) / 256, 256>>>(M);

    // 2) GEMM1: h1 = x @ W1   [M,256]
    {
        dim3 grid(F_HID / 128, (M + 127) / 128);
        sgemm128_kernel<false><<<grid, 256>>>(x, W1, nullptr, h1, M, F_HID, F_IN);
    }

    // 3) layer-1 aggregation: agg1 = self-loop + edge scatter
    {
        long long tot = (long long)M * F_HID;
        self_init_kernel<false><<<(int)((tot + 255) / 256), 256>>>(h1, nullptr, agg1, M, F_HID);
        int blocks = (E * 32 + 255) / 256;  // warp per edge
        scatter_kernel<<<blocks, 256>>>(edges, h1, agg1, E, F_HID);
    }

    // 4) GEMM2: h2 = relu(agg1 + b1) @ W2   [M,128]  (bias+relu fused into A load)
    {
        dim3 grid(F_OUT / 128, (M + 127) / 128);
        sgemm128_kernel<true><<<grid, 256>>>(agg1, W2, b1, h2, M, F_OUT, F_HID);
    }

    // 5) layer-2 aggregation into d_out (self-loop + b2 first, then edge scatter)
    {
        long long tot = (long long)M * F_OUT;
        self_init_kernel<true><<<(int)((tot + 255) / 256), 256>>>(h2, b2, out, M, F_OUT);
        int blocks = (E * 32 + 255) / 256;
        scatter_kernel<<<blocks, 256>>>(edges, h2, out, E, F_OUT);
    }
}

// round 3
// speedup vs baseline: 1.4809x; 1.4809x over previous
#include <cuda_runtime.h>
#include <cstdint>

// GCN: out2 = GCNagg(relu(GCNagg(x@W1) + b1) @ W2) + b2
// GEMMs on mma.sync tf32 (legacy tensor-core path; tcgen05 unavailable:
// harness targets compute_100 base, which rejects all sm_100a features).

#define N_NODES 50000
#define F_IN    256
#define F_HID   256
#define F_OUT   128

// -------- scratch (device globals; no allocations allowed) --------
__device__ float g_h1  [(size_t)N_NODES * F_HID];
__device__ float g_agg1[(size_t)N_NODES * F_HID];
__device__ float g_h2  [(size_t)N_NODES * F_OUT];
__device__ float g_deg [N_NODES];
__device__ float g_dinv[N_NODES];
__device__ int   g_is64;

// ======================= tf32 warp-MMA GEMM =================================
// C[M,N] = op(A)[M,K] @ B[K,N].  BM=BN=128, BK=32, 256 threads (8 warps 2x4).
// Warp tile 64x32 = 4 mfrags x 4 nfrags of m16n8k8.

__device__ __forceinline__ uint32_t f2tf32(float f) {
    uint32_t u;
    asm("cvt.rn.tf32.f32 %0, %1;" : "=r"(u) : "f"(f));
    return u;
}

__device__ __forceinline__ void mma_16x8x8(float* c, const uint32_t* a, const uint32_t* b) {
    asm volatile(
        "mma.sync.aligned.m16n8k8.row.col.f32.tf32.tf32.f32 "
        "{%0,%1,%2,%3}, {%4,%5,%6,%7}, {%8,%9}, {%0,%1,%2,%3};"
        : "+f"(c[0]), "+f"(c[1]), "+f"(c[2]), "+f"(c[3])
        : "r"(a[0]), "r"(a[1]), "r"(a[2]), "r"(a[3]), "r"(b[0]), "r"(b[1]));
}

static constexpr int BM = 128, BN = 128, BK = 32;
static constexpr int APAD = 36;   // words per As row;  36 % 32 == 4  -> a-read banks 4g+t
static constexpr int BPAD = 136;  // words per Bs row; 136 % 32 == 8  -> b-read banks 8t+g

template <bool RELU_BIAS>
__global__ __launch_bounds__(256)
void mma_gemm_kernel(const float* __restrict__ A,
                     const float* __restrict__ B,
                     const float* __restrict__ abias,
                     float* __restrict__ C,
                     int M, int N, int K) {
    __shared__ uint32_t As[BM][APAD];  // [m][k], tf32 bits
    __shared__ uint32_t Bs[BK][BPAD];  // [k][n], tf32 bits

    const int tid  = threadIdx.x;
    const int wid  = tid >> 5;
    const int lane = tid & 31;
    const int g    = lane >> 2;   // groupID (0..7)
    const int t    = lane & 3;    // thread-in-group (0..3)

    const int warp_m = wid >> 2;          // 0..1  -> 64-row slab
    const int warp_n = wid & 3;           // 0..3  -> 32-col slab
    const int wrow = warp_m * 64;
    const int wcol = warp_n * 32;

    const int rowBase = blockIdx.y * BM;
    const int colBase = blockIdx.x * BN;

    float acc[4][4][4];
    #pragma unroll
    for (int i = 0; i < 4; i++)
        #pragma unroll
        for (int j = 0; j < 4; j++)
            #pragma unroll
            for (int c = 0; c < 4; c++) acc[i][j][c] = 0.0f;

    for (int k0 = 0; k0 < K; k0 += BK) {
        // ---- A tile: 128x32 floats, float4 per thread x4 iters ----
        #pragma unroll
        for (int it = 0; it < 2; it++) {
            const int idx = tid + it * 256;          // 0..511
            const int r  = idx >> 3;                  // 0..63  (x2 halves)
            const int c4 = (idx & 7) * 4;
            #pragma unroll
            for (int half = 0; half < 2; half++) {
                const int rr = r + half * 64;
                const int gr = rowBase + rr;
                float4 av = make_float4(0.f, 0.f, 0.f, 0.f);
                if (gr < M)
                    av = *reinterpret_cast<const float4*>(A + (size_t)gr * K + k0 + c4);
                if (RELU_BIAS) {
                    const float4 bv = *reinterpret_cast<const float4*>(abias + k0 + c4);
                    av.x = fmaxf(av.x + bv.x, 0.f);
                    av.y = fmaxf(av.y + bv.y, 0.f);
                    av.z = fmaxf(av.z + bv.z, 0.f);
                    av.w = fmaxf(av.w + bv.w, 0.f);
                }
                uint4 tv;
                tv.x = f2tf32(av.x); tv.y = f2tf32(av.y);
                tv.z = f2tf32(av.z); tv.w = f2tf32(av.w);
                *reinterpret_cast<uint4*>(&As[rr][c4]) = tv;
            }
        }
        // ---- B tile: 32x128 floats ----
        #pragma unroll
        for (int it = 0; it < 4; it++) {
            const int idx = tid + it * 256;
            const int r  = idx >> 5;                  // k row 0..31
            const int c4 = (idx & 31) * 4;
            const float4 bv = *reinterpret_cast<const float4*>(
                B + (size_t)(k0 + r) * N + colBase + c4);
            uint4 tv;
            tv.x = f2tf32(bv.x); tv.y = f2tf32(bv.y);
            tv.z = f2tf32(bv.z); tv.w = f2tf32(bv.w);
            *reinterpret_cast<uint4*>(&Bs[r][c4]) = tv;
        }
        __syncthreads();

        #pragma unroll
        for (int ks = 0; ks < BK / 8; ks++) {
            const int kk = ks * 8;
            uint32_t afrag[4][4], bfrag[4][2];
            #pragma unroll
            for (int i = 0; i < 4; i++) {
                const int rb = wrow + i * 16;
                afrag[i][0] = As[rb + g    ][kk + t    ];
                afrag[i][1] = As[rb + g + 8][kk + t    ];
                afrag[i][2] = As[rb + g    ][kk + t + 4];
                afrag[i][3] = As[rb + g + 8][kk + t + 4];
            }
            #pragma unroll
            for (int j = 0; j < 4; j++) {
                const int nb = wcol + j * 8;
                bfrag[j][0] = Bs[kk + t    ][nb + g];
                bfrag[j][1] = Bs[kk + t + 4][nb + g];
            }
            #pragma unroll
            for (int i = 0; i < 4; i++)
                #pragma unroll
                for (int j = 0; j < 4; j++)
                    mma_16x8x8(acc[i][j], afrag[i], bfrag[j]);
        }
        __syncthreads();
    }

    // ---- epilogue: c0,c1 at (row g, col 2t,2t+1); c2,c3 at row g+8 ----
    #pragma unroll
    for (int i = 0; i < 4; i++) {
        #pragma unroll
        for (int half = 0; half < 2; half++) {
            const int gr = rowBase + wrow + i * 16 + g + half * 8;
            if (gr < M) {
                float* dst = C + (size_t)gr * N + colBase + wcol;
                #pragma unroll
                for (int j = 0; j < 4; j++) {
                    float2 v = make_float2(acc[i][j][half * 2], acc[i][j][half * 2 + 1]);
                    *reinterpret_cast<float2*>(dst + j * 8 + 2 * t) = v;
                }
            }
        }
    }
}

// ======================= graph-side kernels =================================
__global__ void detect_dtype_kernel(const unsigned int* __restrict__ w, int nwords) {
    __shared__ unsigned int s_or;
    if (threadIdx.x == 0) s_or = 0u;
    __syncthreads();
    unsigned int v = 0u;
    for (int i = 2 * threadIdx.x + 1; i < nwords; i += 2 * blockDim.x) v |= w[i];
    atomicOr(&s_or, v);
    __syncthreads();
    if (threadIdx.x == 0) g_is64 = (s_or == 0u) ? 1 : 0;
}

__device__ __forceinline__ long long edge_get(const void* p, long long i) {
    return g_is64 ? ((const long long*)p)[i] : (long long)((const int*)p)[i];
}

__global__ void init_deg_kernel(int n) {
    int i = blockIdx.x * blockDim.x + threadIdx.x;
    if (i < n) g_deg[i] = 1.0f;
}

__global__ void deg_accum_kernel(const void* __restrict__ edges, int E) {
    int e = blockIdx.x * blockDim.x + threadIdx.x;
    if (e < E) atomicAdd(&g_deg[edge_get(edges, e)], 1.0f);
}

__global__ void dinv_kernel(int n) {
    int i = blockIdx.x * blockDim.x + threadIdx.x;
    if (i < n) g_dinv[i] = rsqrtf(g_deg[i]);
}

template <bool ADD_BIAS>
__global__ void self_init_kernel(const float* __restrict__ h,
                                 const float* __restrict__ bias,
                                 float* __restrict__ dst,
                                 int M, int F) {
    long long idx = (long long)blockIdx.x * blockDim.x + threadIdx.x;
    if (idx >= (long long)M * F) return;
    int node = (int)(idx / F);
    int f    = (int)(idx - (long long)node * F);
    float d = g_dinv[node];
    float v = h[idx] * d * d;
    if (ADD_BIAS) v += bias[f];
    dst[idx] = v;
}

__global__ void scatter_kernel(const void* __restrict__ edges,
                               const float* __restrict__ h,
                               float* __restrict__ agg,
                               int E, int F) {
    const int warp = (blockIdx.x * blockDim.x + threadIdx.x) >> 5;
    const int lane = threadIdx.x & 31;
    if (warp >= E) return;
    const long long r = edge_get(edges, warp);
    const long long c = edge_get(edges, (long long)E + warp);
    const float norm = g_dinv[r] * g_dinv[c];
    const float4* __restrict__ src = reinterpret_cast<const float4*>(h + c * F);
    float* __restrict__ dst = agg + r * F;
    const int nf4 = F >> 2;
    for (int i = lane; i < nf4; i += 32) {
        const float4 v = __ldg(&src[i]);
        const int f = i * 4;
        atomicAdd(&dst[f + 0], v.x * norm);
        atomicAdd(&dst[f + 1], v.y * norm);
        atomicAdd(&dst[f + 2], v.z * norm);
        atomicAdd(&dst[f + 3], v.w * norm);
    }
}

// ---------------------------------------------------------------
extern "C" void kernel_launch(void* const* d_in, const int* in_sizes, int n_in,
                              void* d_out, int out_size) {
    const float* x     = (const float*)d_in[0];
    const void*  edges = d_in[1];
    const float* W1    = (const float*)d_in[2];
    const float* b1    = (const float*)d_in[3];
    const float* W2    = (const float*)d_in[4];
    const float* b2    = (const float*)d_in[5];
    float* out = (float*)d_out;

    const int M = in_sizes[0] / F_IN;
    const int E = in_sizes[1] / 2;

    float* h1   = nullptr;  cudaGetSymbolAddress((void**)&h1,   g_h1);
    float* agg1 = nullptr;  cudaGetSymbolAddress((void**)&agg1, g_agg1);
    float* h2   = nullptr;  cudaGetSymbolAddress((void**)&h2,   g_h2);

    // 0) edge dtype detection
    {
        int nwords = 2 * E;
        if (nwords > 4096) nwords = 4096;
        detect_dtype_kernel<<<1, 256>>>((const unsigned int*)edges, nwords);
    }

    // 1) degrees + dinv
    init_deg_kernel<<<(M + 255) / 256, 256>>>(M);
    deg_accum_kernel<<<(E + 255) / 256, 256>>>(edges, E);
    dinv_kernel<<<(M + 255) / 256, 256>>>(M);

    // 2) GEMM1: h1 = x @ W1  [M,256]  (tf32 mma.sync)
    {
        dim3 grid(F_HID / BN, (M + BM - 1) / BM);
        mma_gemm_kernel<false><<<grid, 256>>>(x, W1, nullptr, h1, M, F_HID, F_IN);
    }

    // 3) layer-1 aggregation
    {
        long long tot = (long long)M * F_HID;
        self_init_kernel<false><<<(int)((tot + 255) / 256), 256>>>(h1, nullptr, agg1, M, F_HID);
        int blocks = (E * 32 + 255) / 256;
        scatter_kernel<<<blocks, 256>>>(edges, h1, agg1, E, F_HID);
    }

    // 4) GEMM2: h2 = relu(agg1 + b1) @ W2  [M,128] (bias+relu fused into A load)
    {
        dim3 grid(F_OUT / BN, (M + BM - 1) / BM);
        mma_gemm_kernel<true><<<grid, 256>>>(agg1, W2, b1, h2, M, F_OUT, F_HID);
    }

    // 5) layer-2 aggregation into d_out
    {
        long long tot = (long long)M * F_OUT;
        self_init_kernel<true><<<(int)((tot + 255) / 256), 256>>>(h2, b2, out, M, F_OUT);
        int blocks = (E * 32 + 255) / 256;
        scatter_kernel<<<blocks, 256>>>(edges, h2, out, E, F_OUT);
    }
}

// round 4
// speedup vs baseline: 2.7020x; 1.8245x over previous
#include <cuda_runtime.h>
#include <cstdint>

// GCN: out2 = GCNagg(relu(GCNagg(x@W1) + b1) @ W2) + b2
// Refactor: GEMM epilogues write hs = h*dinv[row] (and init agg with it =
// self loop); scatter adds raw hs[c] via red.global.v4; dinv[r] scaling is
// folded into GEMM2's A-load (layer 1) and a finalize pass (layer 2).

#define N_NODES 50000
#define F_IN    256
#define F_HID   256
#define F_OUT   128

// -------- scratch (device globals; no allocations allowed) --------
__device__ __align__(16) float g_h1  [(size_t)N_NODES * F_HID];  // h1*dinv (scaled)
__device__ __align__(16) float g_agg1[(size_t)N_NODES * F_HID];  // hs1[r] + sum hs1[c]
__device__ __align__(16) float g_h2  [(size_t)N_NODES * F_OUT];  // h2*dinv (scaled)
__device__ float g_deg [N_NODES];
__device__ float g_dinv[N_NODES];
__device__ int   g_is64;

// ======================= tf32 warp-MMA GEMM =================================
// C = op(A) @ B.  BM=BN=128, BK=32, 256 threads (8 warps 2x4), warp tile 64x32.
// A_TRANSFORM: a <- relu(dinv[row]*a + abias[k])   (layer-2 input transform)
// Epilogue: v <- v * dinv[row]; stored to BOTH C1 and C2.

__device__ __forceinline__ uint32_t f2tf32(float f) {
    uint32_t u;
    asm("cvt.rn.tf32.f32 %0, %1;" : "=r"(u) : "f"(f));
    return u;
}

__device__ __forceinline__ void mma_16x8x8(float* c, const uint32_t* a, const uint32_t* b) {
    asm volatile(
        "mma.sync.aligned.m16n8k8.row.col.f32.tf32.tf32.f32 "
        "{%0,%1,%2,%3}, {%4,%5,%6,%7}, {%8,%9}, {%0,%1,%2,%3};"
        : "+f"(c[0]), "+f"(c[1]), "+f"(c[2]), "+f"(c[3])
        : "r"(a[0]), "r"(a[1]), "r"(a[2]), "r"(a[3]), "r"(b[0]), "r"(b[1]));
}

static constexpr int BM = 128, BN = 128, BK = 32;
static constexpr int APAD = 36;   // 36 % 32 == 4  -> a-frag read banks 4g+t (distinct)
static constexpr int BPAD = 136;  // 136 % 32 == 8 -> b-frag read banks 8t+g (distinct)

template <bool A_TRANSFORM>
__global__ __launch_bounds__(256)
void mma_gemm_kernel(const float* __restrict__ A,
                     const float* __restrict__ B,
                     const float* __restrict__ abias,
                     float* __restrict__ C1,
                     float* __restrict__ C2,
                     int M, int N, int K) {
    __shared__ uint32_t As[BM][APAD];  // [m][k], tf32 bits
    __shared__ uint32_t Bs[BK][BPAD];  // [k][n], tf32 bits

    const int tid  = threadIdx.x;
    const int wid  = tid >> 5;
    const int lane = tid & 31;
    const int g    = lane >> 2;
    const int t    = lane & 3;

    const int warp_m = wid >> 2;
    const int warp_n = wid & 3;
    const int wrow = warp_m * 64;
    const int wcol = warp_n * 32;

    const int rowBase = blockIdx.y * BM;
    const int colBase = blockIdx.x * BN;

    float acc[4][4][4];
    #pragma unroll
    for (int i = 0; i < 4; i++)
        #pragma unroll
        for (int j = 0; j < 4; j++)
            #pragma unroll
            for (int c = 0; c < 4; c++) acc[i][j][c] = 0.0f;

    for (int k0 = 0; k0 < K; k0 += BK) {
        // ---- A tile: 128x32 floats ----
        #pragma unroll
        for (int it = 0; it < 2; it++) {
            const int idx = tid + it * 256;
            const int r  = idx >> 3;
            const int c4 = (idx & 7) * 4;
            #pragma unroll
            for (int half = 0; half < 2; half++) {
                const int rr = r + half * 64;
                const int gr = rowBase + rr;
                float4 av = make_float4(0.f, 0.f, 0.f, 0.f);
                if (gr < M) {
                    av = *reinterpret_cast<const float4*>(A + (size_t)gr * K + k0 + c4);
                    if (A_TRANSFORM) {
                        const float d = g_dinv[gr];
                        const float4 bv = *reinterpret_cast<const float4*>(abias + k0 + c4);
                        av.x = fmaxf(fmaf(d, av.x, bv.x), 0.f);
                        av.y = fmaxf(fmaf(d, av.y, bv.y), 0.f);
                        av.z = fmaxf(fmaf(d, av.z, bv.z), 0.f);
                        av.w = fmaxf(fmaf(d, av.w, bv.w), 0.f);
                    }
                }
                uint4 tv;
                tv.x = f2tf32(av.x); tv.y = f2tf32(av.y);
                tv.z = f2tf32(av.z); tv.w = f2tf32(av.w);
                *reinterpret_cast<uint4*>(&As[rr][c4]) = tv;
            }
        }
        // ---- B tile: 32x128 floats ----
        #pragma unroll
        for (int it = 0; it < 4; it++) {
            const int idx = tid + it * 256;
            const int r  = idx >> 5;
            const int c4 = (idx & 31) * 4;
            const float4 bv = *reinterpret_cast<const float4*>(
                B + (size_t)(k0 + r) * N + colBase + c4);
            uint4 tv;
            tv.x = f2tf32(bv.x); tv.y = f2tf32(bv.y);
            tv.z = f2tf32(bv.z); tv.w = f2tf32(bv.w);
            *reinterpret_cast<uint4*>(&Bs[r][c4]) = tv;
        }
        __syncthreads();

        #pragma unroll
        for (int ks = 0; ks < BK / 8; ks++) {
            const int kk = ks * 8;
            uint32_t afrag[4][4], bfrag[4][2];
            #pragma unroll
            for (int i = 0; i < 4; i++) {
                const int rb = wrow + i * 16;
                afrag[i][0] = As[rb + g    ][kk + t    ];
                afrag[i][1] = As[rb + g + 8][kk + t    ];
                afrag[i][2] = As[rb + g    ][kk + t + 4];
                afrag[i][3] = As[rb + g + 8][kk + t + 4];
            }
            #pragma unroll
            for (int j = 0; j < 4; j++) {
                const int nb = wcol + j * 8;
                bfrag[j][0] = Bs[kk + t    ][nb + g];
                bfrag[j][1] = Bs[kk + t + 4][nb + g];
            }
            #pragma unroll
            for (int i = 0; i < 4; i++)
                #pragma unroll
                for (int j = 0; j < 4; j++)
                    mma_16x8x8(acc[i][j], afrag[i], bfrag[j]);
        }
        __syncthreads();
    }

    // ---- epilogue: scale by dinv[row]; write to C1 and C2 ----
    #pragma unroll
    for (int i = 0; i < 4; i++) {
        #pragma unroll
        for (int half = 0; half < 2; half++) {
            const int gr = rowBase + wrow + i * 16 + g + half * 8;
            if (gr < M) {
                const float d = g_dinv[gr];
                float* dst1 = C1 + (size_t)gr * N + colBase + wcol;
                float* dst2 = C2 + (size_t)gr * N + colBase + wcol;
                #pragma unroll
                for (int j = 0; j < 4; j++) {
                    float2 v = make_float2(acc[i][j][half * 2] * d,
                                           acc[i][j][half * 2 + 1] * d);
                    *reinterpret_cast<float2*>(dst1 + j * 8 + 2 * t) = v;
                    *reinterpret_cast<float2*>(dst2 + j * 8 + 2 * t) = v;
                }
            }
        }
    }
}

// ======================= graph-side kernels =================================
__global__ void detect_dtype_kernel(const unsigned int* __restrict__ w, int nwords) {
    __shared__ unsigned int s_or;
    if (threadIdx.x == 0) s_or = 0u;
    __syncthreads();
    unsigned int v = 0u;
    for (int i = 2 * threadIdx.x + 1; i < nwords; i += 2 * blockDim.x) v |= w[i];
    atomicOr(&s_or, v);
    __syncthreads();
    if (threadIdx.x == 0) g_is64 = (s_or == 0u) ? 1 : 0;
}

__device__ __forceinline__ long long edge_get(const void* p, long long i) {
    return g_is64 ? ((const long long*)p)[i] : (long long)((const int*)p)[i];
}

__global__ void init_deg_kernel(int n) {
    int i = blockIdx.x * blockDim.x + threadIdx.x;
    if (i < n) g_deg[i] = 1.0f;
}

__global__ void deg_accum_kernel(const void* __restrict__ edges, int E) {
    int e = blockIdx.x * blockDim.x + threadIdx.x;
    if (e < E) atomicAdd(&g_deg[edge_get(edges, e)], 1.0f);
}

__global__ void dinv_kernel(int n) {
    int i = blockIdx.x * blockDim.x + threadIdx.x;
    if (i < n) g_dinv[i] = rsqrtf(g_deg[i]);
}

// -------- edge scatter: agg[r,:] += hs[c,:]  (no norm; hs is pre-scaled) ----
__global__ void scatter_kernel(const void* __restrict__ edges,
                               const float* __restrict__ hs,
                               float* __restrict__ agg,
                               int E, int F) {
    const int warp = (blockIdx.x * blockDim.x + threadIdx.x) >> 5;
    const int lane = threadIdx.x & 31;
    if (warp >= E) return;
    const long long r = edge_get(edges, warp);                 // destination
    const long long c = edge_get(edges, (long long)E + warp);  // source
    const float4* __restrict__ src = reinterpret_cast<const float4*>(hs + c * F);
    float* __restrict__ dst = agg + r * F;
    const int nf4 = F >> 2;
    for (int i = lane; i < nf4; i += 32) {
        const float4 v = __ldg(&src[i]);
        asm volatile("red.global.add.v4.f32 [%0], {%1,%2,%3,%4};"
                     :: "l"(dst + 4 * i), "f"(v.x), "f"(v.y), "f"(v.z), "f"(v.w)
                     : "memory");
    }
}

// -------- finalize layer 2: out = dinv[node]*out + b2[f] --------
__global__ void finalize_kernel(float* __restrict__ out,
                                const float* __restrict__ b2,
                                int M, int F) {
    const int nf4 = F >> 2;
    long long idx = (long long)blockIdx.x * blockDim.x + threadIdx.x;
    if (idx >= (long long)M * nf4) return;
    const int node = (int)(idx / nf4);
    const int f4   = (int)(idx - (long long)node * nf4);
    const float d = g_dinv[node];
    float4 v = reinterpret_cast<float4*>(out)[idx];
    const float4 bv = reinterpret_cast<const float4*>(b2)[f4];
    v.x = fmaf(d, v.x, bv.x);
    v.y = fmaf(d, v.y, bv.y);
    v.z = fmaf(d, v.z, bv.z);
    v.w = fmaf(d, v.w, bv.w);
    reinterpret_cast<float4*>(out)[idx] = v;
}

// ---------------------------------------------------------------
extern "C" void kernel_launch(void* const* d_in, const int* in_sizes, int n_in,
                              void* d_out, int out_size) {
    const float* x     = (const float*)d_in[0];
    const void*  edges = d_in[1];
    const float* W1    = (const float*)d_in[2];
    const float* b1    = (const float*)d_in[3];
    const float* W2    = (const float*)d_in[4];
    const float* b2    = (const float*)d_in[5];
    float* out = (float*)d_out;

    const int M = in_sizes[0] / F_IN;
    const int E = in_sizes[1] / 2;

    float* h1   = nullptr;  cudaGetSymbolAddress((void**)&h1,   g_h1);
    float* agg1 = nullptr;  cudaGetSymbolAddress((void**)&agg1, g_agg1);
    float* h2   = nullptr;  cudaGetSymbolAddress((void**)&h2,   g_h2);

    // 0) edge dtype detection
    {
        int nwords = 2 * E;
        if (nwords > 4096) nwords = 4096;
        detect_dtype_kernel<<<1, 256>>>((const unsigned int*)edges, nwords);
    }

    // 1) degrees + dinv
    init_deg_kernel<<<(M + 255) / 256, 256>>>(M);
    deg_accum_kernel<<<(E + 255) / 256, 256>>>(edges, E);
    dinv_kernel<<<(M + 255) / 256, 256>>>(M);

    // 2) GEMM1: hs1 = (x @ W1) * dinv[row] -> g_h1, and init agg1 = hs1 (self loop)
    {
        dim3 grid(F_HID / BN, (M + BM - 1) / BM);
        mma_gemm_kernel<false><<<grid, 256>>>(x, W1, nullptr, h1, agg1, M, F_HID, F_IN);
    }

    // 3) layer-1 edge scatter: agg1[r] += hs1[c]
    {
        int blocks = (E * 32 + 255) / 256;
        scatter_kernel<<<blocks, 256>>>(edges, h1, agg1, E, F_HID);
    }

    // 4) GEMM2: A-load = relu(dinv[row]*agg1 + b1); hs2 = (A @ W2)*dinv[row]
    //    -> g_h2, and init out = hs2 (self loop)
    {
        dim3 grid(F_OUT / BN, (M + BM - 1) / BM);
        mma_gemm_kernel<true><<<grid, 256>>>(agg1, W2, b1, h2, out, M, F_OUT, F_HID);
    }

    // 5) layer-2 edge scatter: out[r] += hs2[c]
    {
        int blocks = (E * 32 + 255) / 256;
        scatter_kernel<<<blocks, 256>>>(edges, h2, out, E, F_OUT);
    }

    // 6) finalize: out = dinv[node]*out + b2
    {
        long long tot = (long long)M * (F_OUT / 4);
        finalize_kernel<<<(int)((tot + 255) / 256), 256>>>(out, b2, M, F_OUT);
    }
}

// round 5
// speedup vs baseline: 3.5142x; 1.3006x over previous
#include <cuda_runtime.h>
#include <cstdint>

// GCN: out2 = GCNagg(relu(GCNagg(x@W1) + b1) @ W2) + b2
// R5: CSR-by-destination gather aggregation (no atomics on features),
//     register-staged pipelined tf32 mma.sync GEMM, bias/relu/dinv folded
//     into the gather epilogue.

#define N_NODES 50000
#define F_IN    256
#define F_HID   256
#define F_OUT   128
#define MAX_E   320000

// -------- scratch (device globals; no allocations allowed) --------
__device__ __align__(16) float g_h1  [(size_t)N_NODES * F_HID];  // (x@W1)*dinv[row]
__device__ __align__(16) float g_agg1[(size_t)N_NODES * F_HID];  // layer-2 input
__device__ __align__(16) float g_h2  [(size_t)N_NODES * F_OUT];  // (agg1@W2)*dinv[row]
__device__ float g_dinv  [N_NODES];
__device__ int   g_indeg [N_NODES];
__device__ int   g_off   [N_NODES + 1];
__device__ int   g_cursor[N_NODES];
__device__ int   g_bsum  [256];
__device__ int   g_elist [MAX_E];
__device__ int   g_is64;

// ======================= tf32 warp-MMA GEMM (pipelined) =====================
// C = A @ B, epilogue scale by dinv[row].  BM=BN=128, BK=32, 256 threads,
// 8 warps (2x4), warp tile 64x32 of m16n8k8. Next K-tile staged in registers
// while current smem tile is consumed.

__device__ __forceinline__ uint32_t f2tf32(float f) {
    uint32_t u;
    asm("cvt.rn.tf32.f32 %0, %1;" : "=r"(u) : "f"(f));
    return u;
}

__device__ __forceinline__ void mma_16x8x8(float* c, const uint32_t* a, const uint32_t* b) {
    asm volatile(
        "mma.sync.aligned.m16n8k8.row.col.f32.tf32.tf32.f32 "
        "{%0,%1,%2,%3}, {%4,%5,%6,%7}, {%8,%9}, {%0,%1,%2,%3};"
        : "+f"(c[0]), "+f"(c[1]), "+f"(c[2]), "+f"(c[3])
        : "r"(a[0]), "r"(a[1]), "r"(a[2]), "r"(a[3]), "r"(b[0]), "r"(b[1]));
}

static constexpr int BM = 128, BN = 128, BK = 32;
static constexpr int APAD = 36;   // 36 % 32 == 4  -> a-frag banks 4g+t (distinct)
static constexpr int BPAD = 136;  // 136 % 32 == 8 -> b-frag banks 8t+g (distinct)

__global__ __launch_bounds__(256)
void mma_gemm_kernel(const float* __restrict__ A,
                     const float* __restrict__ B,
                     float* __restrict__ C,
                     int M, int N, int K) {
    __shared__ uint32_t As[BM][APAD];  // [m][k]
    __shared__ uint32_t Bs[BK][BPAD];  // [k][n]

    const int tid  = threadIdx.x;
    const int wid  = tid >> 5;
    const int lane = tid & 31;
    const int g    = lane >> 2;
    const int t    = lane & 3;
    const int wrow = (wid >> 2) * 64;
    const int wcol = (wid & 3) * 32;
    const int rowBase = blockIdx.y * BM;
    const int colBase = blockIdx.x * BN;

    // load mappings (4 float4 per thread for each tile)
    const int ar  = tid >> 1;            // via idx = tid + it*256: r = idx>>3
    // we use: A idx = tid + it*256 -> r = idx>>3 (0..127), c4 = (idx&7)*4
    //         B idx = tid + it*256 -> r = idx>>5 (0..31),  c4 = (idx&31)*4
    (void)ar;

    float4 a_stage[4], b_stage[4];

    auto load_stage = [&](int k0) {
        #pragma unroll
        for (int it = 0; it < 4; it++) {
            const int idx = tid + it * 256;
            const int r  = idx >> 3;
            const int c4 = (idx & 7) * 4;
            const int gr = rowBase + r;
            a_stage[it] = (gr < M)
                ? *reinterpret_cast<const float4*>(A + (size_t)gr * K + k0 + c4)
                : make_float4(0.f, 0.f, 0.f, 0.f);
        }
        #pragma unroll
        for (int it = 0; it < 4; it++) {
            const int idx = tid + it * 256;
            const int r  = idx >> 5;
            const int c4 = (idx & 31) * 4;
            b_stage[it] = *reinterpret_cast<const float4*>(
                B + (size_t)(k0 + r) * N + colBase + c4);
        }
    };

    auto store_stage = [&]() {
        #pragma unroll
        for (int it = 0; it < 4; it++) {
            const int idx = tid + it * 256;
            const int r  = idx >> 3;
            const int c4 = (idx & 7) * 4;
            uint4 tv;
            tv.x = f2tf32(a_stage[it].x); tv.y = f2tf32(a_stage[it].y);
            tv.z = f2tf32(a_stage[it].z); tv.w = f2tf32(a_stage[it].w);
            *reinterpret_cast<uint4*>(&As[r][c4]) = tv;
        }
        #pragma unroll
        for (int it = 0; it < 4; it++) {
            const int idx = tid + it * 256;
            const int r  = idx >> 5;
            const int c4 = (idx & 31) * 4;
            uint4 tv;
            tv.x = f2tf32(b_stage[it].x); tv.y = f2tf32(b_stage[it].y);
            tv.z = f2tf32(b_stage[it].z); tv.w = f2tf32(b_stage[it].w);
            *reinterpret_cast<uint4*>(&Bs[r][c4]) = tv;
        }
    };

    float acc[4][4][4];
    #pragma unroll
    for (int i = 0; i < 4; i++)
        #pragma unroll
        for (int j = 0; j < 4; j++)
            #pragma unroll
            for (int c = 0; c < 4; c++) acc[i][j][c] = 0.0f;

    load_stage(0);

    for (int k0 = 0; k0 < K; k0 += BK) {
        store_stage();
        __syncthreads();
        if (k0 + BK < K) load_stage(k0 + BK);   // LDGs overlap with MMA below

        #pragma unroll
        for (int ks = 0; ks < BK / 8; ks++) {
            const int kk = ks * 8;
            uint32_t afrag[4][4], bfrag[4][2];
            #pragma unroll
            for (int i = 0; i < 4; i++) {
                const int rb = wrow + i * 16;
                afrag[i][0] = As[rb + g    ][kk + t    ];
                afrag[i][1] = As[rb + g + 8][kk + t    ];
                afrag[i][2] = As[rb + g    ][kk + t + 4];
                afrag[i][3] = As[rb + g + 8][kk + t + 4];
            }
            #pragma unroll
            for (int j = 0; j < 4; j++) {
                const int nb = wcol + j * 8;
                bfrag[j][0] = Bs[kk + t    ][nb + g];
                bfrag[j][1] = Bs[kk + t + 4][nb + g];
            }
            #pragma unroll
            for (int i = 0; i < 4; i++)
                #pragma unroll
                for (int j = 0; j < 4; j++)
                    mma_16x8x8(acc[i][j], afrag[i], bfrag[j]);
        }
        __syncthreads();
    }

    // ---- epilogue: scale by dinv[row], single output ----
    #pragma unroll
    for (int i = 0; i < 4; i++) {
        #pragma unroll
        for (int half = 0; half < 2; half++) {
            const int gr = rowBase + wrow + i * 16 + g + half * 8;
            if (gr < M) {
                const float d = g_dinv[gr];
                float* dst = C + (size_t)gr * N + colBase + wcol;
                #pragma unroll
                for (int j = 0; j < 4; j++) {
                    float2 v = make_float2(acc[i][j][half * 2] * d,
                                           acc[i][j][half * 2 + 1] * d);
                    *reinterpret_cast<float2*>(dst + j * 8 + 2 * t) = v;
                }
            }
        }
    }
}

// ======================= graph-side kernels =================================
__global__ void detect_dtype_kernel(const unsigned int* __restrict__ w, int nwords) {
    __shared__ unsigned int s_or;
    if (threadIdx.x == 0) s_or = 0u;
    __syncthreads();
    unsigned int v = 0u;
    for (int i = 2 * threadIdx.x + 1; i < nwords; i += 2 * blockDim.x) v |= w[i];
    atomicOr(&s_or, v);
    __syncthreads();
    if (threadIdx.x == 0) g_is64 = (s_or == 0u) ? 1 : 0;
}

__device__ __forceinline__ long long edge_get(const void* p, long long i) {
    return g_is64 ? ((const long long*)p)[i] : (long long)((const int*)p)[i];
}

__global__ void init_indeg_kernel(int n) {
    int i = blockIdx.x * blockDim.x + threadIdx.x;
    if (i < n) g_indeg[i] = 0;
}

__global__ void indeg_kernel(const void* __restrict__ edges, int E) {
    int e = blockIdx.x * blockDim.x + threadIdx.x;
    if (e < E) atomicAdd(&g_indeg[(int)edge_get(edges, e)], 1);
}

__global__ void dinv_kernel(int n) {
    int i = blockIdx.x * blockDim.x + threadIdx.x;
    if (i < n) g_dinv[i] = rsqrtf((float)(g_indeg[i] + 1));
}

// ---- prefix sum over indeg -> g_off (exclusive), g_cursor = segment starts --
__global__ void scanA_kernel(int n) {   // per-256 block inclusive scan
    __shared__ int s[256];
    const int t = threadIdx.x;
    const int i = blockIdx.x * 256 + t;
    int v = (i < n) ? g_indeg[i] : 0;
    s[t] = v;
    __syncthreads();
    #pragma unroll
    for (int off = 1; off < 256; off <<= 1) {
        int x = (t >= off) ? s[t - off] : 0;
        __syncthreads();
        s[t] += x;
        __syncthreads();
    }
    if (i < n) g_off[i + 1] = s[t];
    if (t == 255) g_bsum[blockIdx.x] = s[255];
}

__global__ void scanB_kernel(int nb) {  // scan the block sums (nb <= 256)
    __shared__ int s[256];
    const int t = threadIdx.x;
    s[t] = (t < nb) ? g_bsum[t] : 0;
    __syncthreads();
    #pragma unroll
    for (int off = 1; off < 256; off <<= 1) {
        int x = (t >= off) ? s[t - off] : 0;
        __syncthreads();
        s[t] += x;
        __syncthreads();
    }
    if (t < nb) g_bsum[t] = s[t];
}

__global__ void scanC_kernel(int n) {   // add block prefixes, emit cursors
    int i = blockIdx.x * blockDim.x + threadIdx.x;
    if (i >= n) return;
    const int b = i >> 8;
    const int add = (b > 0) ? g_bsum[b - 1] : 0;
    const int fin = g_off[i + 1] + add;
    g_off[i + 1] = fin;
    if (i + 1 < n) g_cursor[i + 1] = fin;
    if (i == 0) { g_off[0] = 0; g_cursor[0] = 0; }
}

__global__ void fill_kernel(const void* __restrict__ edges, int E) {
    int e = blockIdx.x * blockDim.x + threadIdx.x;
    if (e >= E) return;
    const int r = (int)edge_get(edges, e);                 // destination
    const int c = (int)edge_get(edges, (long long)E + e);  // source
    const int slot = atomicAdd(&g_cursor[r], 1);
    g_elist[slot] = c;
}

// ---- gather aggregation: warp per destination node ----
// out[r] = post( dinv[r] * (hs[r] + sum_{c in nbr(r)} hs[c]) + bias )
template <int F, bool RELU>
__global__ void gather_kernel(const float* __restrict__ hs,
                              const float* __restrict__ bias,
                              float* __restrict__ outp,
                              int M) {
    const int node = (int)((blockIdx.x * blockDim.x + threadIdx.x) >> 5);
    const int lane = threadIdx.x & 31;
    if (node >= M) return;
    constexpr int NSEG = F / 128;   // float4 per lane

    float4 acc[NSEG];
    const float4* self = reinterpret_cast<const float4*>(hs + (size_t)node * F);
    #pragma unroll
    for (int s = 0; s < NSEG; s++) acc[s] = __ldg(&self[lane + 32 * s]);

    const int beg = g_off[node];
    const int end = g_off[node + 1];
    for (int i = beg; i < end; i += 32) {
        const int my = (i + lane < end) ? g_elist[i + lane] : 0;
        const int cnt = min(32, end - i);
        for (int j = 0; j < cnt; j++) {
            const int c = __shfl_sync(0xffffffffu, my, j);
            const float4* src = reinterpret_cast<const float4*>(hs + (size_t)c * F);
            #pragma unroll
            for (int s = 0; s < NSEG; s++) {
                const float4 v = __ldg(&src[lane + 32 * s]);
                acc[s].x += v.x; acc[s].y += v.y;
                acc[s].z += v.z; acc[s].w += v.w;
            }
        }
    }

    const float d = g_dinv[node];
    float4* dst = reinterpret_cast<float4*>(outp + (size_t)node * F);
    const float4* bp = reinterpret_cast<const float4*>(bias);
    #pragma unroll
    for (int s = 0; s < NSEG; s++) {
        const float4 bv = __ldg(&bp[lane + 32 * s]);
        float4 v;
        v.x = fmaf(d, acc[s].x, bv.x);
        v.y = fmaf(d, acc[s].y, bv.y);
        v.z = fmaf(d, acc[s].z, bv.z);
        v.w = fmaf(d, acc[s].w, bv.w);
        if (RELU) {
            v.x = fmaxf(v.x, 0.f); v.y = fmaxf(v.y, 0.f);
            v.z = fmaxf(v.z, 0.f); v.w = fmaxf(v.w, 0.f);
        }
        dst[lane + 32 * s] = v;
    }
}

// ---------------------------------------------------------------
extern "C" void kernel_launch(void* const* d_in, const int* in_sizes, int n_in,
                              void* d_out, int out_size) {
    const float* x     = (const float*)d_in[0];
    const void*  edges = d_in[1];
    const float* W1    = (const float*)d_in[2];
    const float* b1    = (const float*)d_in[3];
    const float* W2    = (const float*)d_in[4];
    const float* b2    = (const float*)d_in[5];
    float* out = (float*)d_out;

    const int M = in_sizes[0] / F_IN;
    const int E = in_sizes[1] / 2;
    const int NB = (M + 255) / 256;

    float* h1   = nullptr;  cudaGetSymbolAddress((void**)&h1,   g_h1);
    float* agg1 = nullptr;  cudaGetSymbolAddress((void**)&agg1, g_agg1);
    float* h2   = nullptr;  cudaGetSymbolAddress((void**)&h2,   g_h2);

    // 0) edge dtype detection
    {
        int nwords = 2 * E;
        if (nwords > 4096) nwords = 4096;
        detect_dtype_kernel<<<1, 256>>>((const unsigned int*)edges, nwords);
    }

    // 1) degrees + dinv + CSR(dst) build
    init_indeg_kernel<<<NB, 256>>>(M);
    indeg_kernel<<<(E + 255) / 256, 256>>>(edges, E);
    dinv_kernel<<<NB, 256>>>(M);
    scanA_kernel<<<NB, 256>>>(M);
    scanB_kernel<<<1, 256>>>(NB);
    scanC_kernel<<<NB, 256>>>(M);
    fill_kernel<<<(E + 255) / 256, 256>>>(edges, E);

    // 2) GEMM1: hs1 = (x @ W1) * dinv[row]
    {
        dim3 grid(F_HID / BN, (M + BM - 1) / BM);
        mma_gemm_kernel<<<grid, 256>>>(x, W1, h1, M, F_HID, F_IN);
    }

    // 3) gather1: agg1[r] = relu(dinv[r]*(hs1[r] + sum hs1[c]) + b1)
    {
        const long long threads = (long long)M * 32;
        gather_kernel<F_HID, true><<<(int)((threads + 255) / 256), 256>>>(h1, b1, agg1, M);
    }

    // 4) GEMM2: hs2 = (agg1 @ W2) * dinv[row]
    {
        dim3 grid(F_OUT / BN, (M + BM - 1) / BM);
        mma_gemm_kernel<<<grid, 256>>>(agg1, W2, h2, M, F_OUT, F_HID);
    }

    // 5) gather2: out[r] = dinv[r]*(hs2[r] + sum hs2[c]) + b2
    {
        const long long threads = (long long)M * 32;
        gather_kernel<F_OUT, false><<<(int)((threads + 255) / 256), 256>>>(h2, b2, out, M);
    }
}

// round 6
// speedup vs baseline: 3.9146x; 1.1139x over previous
#include <cuda_runtime.h>
#include <cstdint>

// GCN: out2 = GCNagg(relu(GCNagg(x@W1) + b1) @ W2) + b2
// R6: CSR build overlapped with GEMM1 on a forked capture stream (GEMM1 is
//     now dinv-free; gather1 applies per-neighbor dinv[c]); double-buffered
//     single-sync GEMM mainloop.

#define N_NODES 50000
#define F_IN    256
#define F_HID   256
#define F_OUT   128
#define MAX_E   320000

// -------- scratch (device globals; no allocations allowed) --------
__device__ __align__(16) float g_h1  [(size_t)N_NODES * F_HID];  // x@W1 (raw)
__device__ __align__(16) float g_agg1[(size_t)N_NODES * F_HID];  // layer-2 input
__device__ __align__(16) float g_h2  [(size_t)N_NODES * F_OUT];  // (agg1@W2)*dinv
__device__ float g_dinv  [N_NODES];
__device__ int   g_indeg [N_NODES];
__device__ int   g_off   [N_NODES + 1];
__device__ int   g_cursor[N_NODES];
__device__ int   g_bsum  [256];
__device__ int   g_elist [MAX_E];
__device__ int   g_is64;

// ======================= tf32 warp-MMA GEMM (double-buffered) ===============
__device__ __forceinline__ uint32_t f2tf32(float f) {
    uint32_t u;
    asm("cvt.rn.tf32.f32 %0, %1;" : "=r"(u) : "f"(f));
    return u;
}

__device__ __forceinline__ void mma_16x8x8(float* c, const uint32_t* a, const uint32_t* b) {
    asm volatile(
        "mma.sync.aligned.m16n8k8.row.col.f32.tf32.tf32.f32 "
        "{%0,%1,%2,%3}, {%4,%5,%6,%7}, {%8,%9}, {%0,%1,%2,%3};"
        : "+f"(c[0]), "+f"(c[1]), "+f"(c[2]), "+f"(c[3])
        : "r"(a[0]), "r"(a[1]), "r"(a[2]), "r"(a[3]), "r"(b[0]), "r"(b[1]));
}

static constexpr int BM = 128, BN = 128, BK = 32;
static constexpr int APAD = 36;   // 36 % 32 == 4  -> a-frag banks 4g+t (distinct)
static constexpr int BPAD = 136;  // 136 % 32 == 8 -> b-frag banks 8t+g (distinct)
static constexpr int ASZ = BM * APAD;          // words
static constexpr int BSZ = BK * BPAD;          // words
static constexpr int STAGE = ASZ + BSZ;        // words per buffer
static constexpr int GEMM_SMEM = 2 * STAGE * 4;  // bytes (~70KB)

template <bool SCALE_EPI>
__global__ __launch_bounds__(256)
void mma_gemm_kernel(const float* __restrict__ A,
                     const float* __restrict__ B,
                     float* __restrict__ C,
                     int M, int N, int K) {
    extern __shared__ uint32_t smem[];

    const int tid  = threadIdx.x;
    const int wid  = tid >> 5;
    const int lane = tid & 31;
    const int g    = lane >> 2;
    const int t    = lane & 3;
    const int wrow = (wid >> 2) * 64;
    const int wcol = (wid & 3) * 32;
    const int rowBase = blockIdx.y * BM;
    const int colBase = blockIdx.x * BN;

    float4 a_stage[4], b_stage[4];

    auto load_stage = [&](int k0) {
        #pragma unroll
        for (int it = 0; it < 4; it++) {
            const int idx = tid + it * 256;
            const int r  = idx >> 3;
            const int c4 = (idx & 7) * 4;
            const int gr = rowBase + r;
            a_stage[it] = (gr < M)
                ? *reinterpret_cast<const float4*>(A + (size_t)gr * K + k0 + c4)
                : make_float4(0.f, 0.f, 0.f, 0.f);
        }
        #pragma unroll
        for (int it = 0; it < 4; it++) {
            const int idx = tid + it * 256;
            const int r  = idx >> 5;
            const int c4 = (idx & 31) * 4;
            b_stage[it] = *reinterpret_cast<const float4*>(
                B + (size_t)(k0 + r) * N + colBase + c4);
        }
    };

    auto store_stage = [&](uint32_t* As, uint32_t* Bs) {
        #pragma unroll
        for (int it = 0; it < 4; it++) {
            const int idx = tid + it * 256;
            const int r  = idx >> 3;
            const int c4 = (idx & 7) * 4;
            uint4 tv;
            tv.x = f2tf32(a_stage[it].x); tv.y = f2tf32(a_stage[it].y);
            tv.z = f2tf32(a_stage[it].z); tv.w = f2tf32(a_stage[it].w);
            *reinterpret_cast<uint4*>(&As[r * APAD + c4]) = tv;
        }
        #pragma unroll
        for (int it = 0; it < 4; it++) {
            const int idx = tid + it * 256;
            const int r  = idx >> 5;
            const int c4 = (idx & 31) * 4;
            uint4 tv;
            tv.x = f2tf32(b_stage[it].x); tv.y = f2tf32(b_stage[it].y);
            tv.z = f2tf32(b_stage[it].z); tv.w = f2tf32(b_stage[it].w);
            *reinterpret_cast<uint4*>(&Bs[r * BPAD + c4]) = tv;
        }
    };

    float acc[4][4][4];
    #pragma unroll
    for (int i = 0; i < 4; i++)
        #pragma unroll
        for (int j = 0; j < 4; j++)
            #pragma unroll
            for (int c = 0; c < 4; c++) acc[i][j][c] = 0.0f;

    load_stage(0);

    const int ntiles = K / BK;
    for (int it = 0; it < ntiles; it++) {
        uint32_t* As = smem + (it & 1) * STAGE;
        uint32_t* Bs = As + ASZ;

        store_stage(As, Bs);
        __syncthreads();                          // single sync per tile
        if (it + 1 < ntiles) load_stage((it + 1) * BK);  // LDGs overlap MMA

        #pragma unroll
        for (int ks = 0; ks < BK / 8; ks++) {
            const int kk = ks * 8;
            uint32_t afrag[4][4], bfrag[4][2];
            #pragma unroll
            for (int i = 0; i < 4; i++) {
                const int rb = wrow + i * 16;
                afrag[i][0] = As[(rb + g    ) * APAD + kk + t    ];
                afrag[i][1] = As[(rb + g + 8) * APAD + kk + t    ];
                afrag[i][2] = As[(rb + g    ) * APAD + kk + t + 4];
                afrag[i][3] = As[(rb + g + 8) * APAD + kk + t + 4];
            }
            #pragma unroll
            for (int j = 0; j < 4; j++) {
                const int nb = wcol + j * 8;
                bfrag[j][0] = Bs[(kk + t    ) * BPAD + nb + g];
                bfrag[j][1] = Bs[(kk + t + 4) * BPAD + nb + g];
            }
            #pragma unroll
            for (int i = 0; i < 4; i++)
                #pragma unroll
                for (int j = 0; j < 4; j++)
                    mma_16x8x8(acc[i][j], afrag[i], bfrag[j]);
        }
    }

    // ---- epilogue ----
    #pragma unroll
    for (int i = 0; i < 4; i++) {
        #pragma unroll
        for (int half = 0; half < 2; half++) {
            const int gr = rowBase + wrow + i * 16 + g + half * 8;
            if (gr < M) {
                const float d = SCALE_EPI ? g_dinv[gr] : 1.0f;
                float* dst = C + (size_t)gr * N + colBase + wcol;
                #pragma unroll
                for (int j = 0; j < 4; j++) {
                    float2 v = make_float2(acc[i][j][half * 2] * d,
                                           acc[i][j][half * 2 + 1] * d);
                    *reinterpret_cast<float2*>(dst + j * 8 + 2 * t) = v;
                }
            }
        }
    }
}

// ======================= graph-side kernels =================================
__global__ void detect_dtype_kernel(const unsigned int* __restrict__ w, int nwords) {
    __shared__ unsigned int s_or;
    if (threadIdx.x == 0) s_or = 0u;
    __syncthreads();
    unsigned int v = 0u;
    for (int i = 2 * threadIdx.x + 1; i < nwords; i += 2 * blockDim.x) v |= w[i];
    atomicOr(&s_or, v);
    __syncthreads();
    if (threadIdx.x == 0) g_is64 = (s_or == 0u) ? 1 : 0;
}

__device__ __forceinline__ long long edge_get(const void* p, long long i) {
    return g_is64 ? ((const long long*)p)[i] : (long long)((const int*)p)[i];
}

__global__ void init_indeg_kernel(int n) {
    int i = blockIdx.x * blockDim.x + threadIdx.x;
    if (i < n) g_indeg[i] = 0;
}

__global__ void indeg_kernel(const void* __restrict__ edges, int E) {
    int e = blockIdx.x * blockDim.x + threadIdx.x;
    if (e < E) atomicAdd(&g_indeg[(int)edge_get(edges, e)], 1);
}

// block scan; also computes dinv = rsqrt(indeg+1)
__global__ void scanA_kernel(int n) {
    __shared__ int s[256];
    const int t = threadIdx.x;
    const int i = blockIdx.x * 256 + t;
    int v = 0;
    if (i < n) {
        v = g_indeg[i];
        g_dinv[i] = rsqrtf((float)(v + 1));
    }
    s[t] = v;
    __syncthreads();
    #pragma unroll
    for (int off = 1; off < 256; off <<= 1) {
        int x = (t >= off) ? s[t - off] : 0;
        __syncthreads();
        s[t] += x;
        __syncthreads();
    }
    if (i < n) g_off[i + 1] = s[t];
    if (t == 255) g_bsum[blockIdx.x] = s[255];
}

__global__ void scanB_kernel(int nb) {
    __shared__ int s[256];
    const int t = threadIdx.x;
    s[t] = (t < nb) ? g_bsum[t] : 0;
    __syncthreads();
    #pragma unroll
    for (int off = 1; off < 256; off <<= 1) {
        int x = (t >= off) ? s[t - off] : 0;
        __syncthreads();
        s[t] += x;
        __syncthreads();
    }
    if (t < nb) g_bsum[t] = s[t];
}

__global__ void scanC_kernel(int n) {
    int i = blockIdx.x * blockDim.x + threadIdx.x;
    if (i >= n) return;
    const int b = i >> 8;
    const int add = (b > 0) ? g_bsum[b - 1] : 0;
    const int fin = g_off[i + 1] + add;
    g_off[i + 1] = fin;
    if (i + 1 < n) g_cursor[i + 1] = fin;
    if (i == 0) { g_off[0] = 0; g_cursor[0] = 0; }
}

__global__ void fill_kernel(const void* __restrict__ edges, int E) {
    int e = blockIdx.x * blockDim.x + threadIdx.x;
    if (e >= E) return;
    const int r = (int)edge_get(edges, e);                 // destination
    const int c = (int)edge_get(edges, (long long)E + e);  // source
    const int slot = atomicAdd(&g_cursor[r], 1);
    g_elist[slot] = c;
}

// ---- gather aggregation: warp per destination node ----
// SCALE_NBR=1: out[r] = post(dinv[r]*(dinv[r]*h[r] + sum dinv[c]*h[c]) + bias)
// SCALE_NBR=0: out[r] = post(dinv[r]*(hs[r] + sum hs[c]) + bias)  (hs pre-scaled)
template <int F, bool RELU, bool SCALE_NBR>
__global__ void gather_kernel(const float* __restrict__ hs,
                              const float* __restrict__ bias,
                              float* __restrict__ outp,
                              int M) {
    const int node = (int)((blockIdx.x * blockDim.x + threadIdx.x) >> 5);
    const int lane = threadIdx.x & 31;
    if (node >= M) return;
    constexpr int NSEG = F / 128;

    const float d = g_dinv[node];
    const float selfs = SCALE_NBR ? d : 1.0f;

    float4 acc[NSEG];
    const float4* self = reinterpret_cast<const float4*>(hs + (size_t)node * F);
    #pragma unroll
    for (int s = 0; s < NSEG; s++) {
        const float4 v = __ldg(&self[lane + 32 * s]);
        acc[s] = make_float4(v.x * selfs, v.y * selfs, v.z * selfs, v.w * selfs);
    }

    const int beg = g_off[node];
    const int end = g_off[node + 1];
    for (int i = beg; i < end; i += 32) {
        const int my  = (i + lane < end) ? g_elist[i + lane] : 0;
        const float myd = SCALE_NBR ? g_dinv[my] : 1.0f;
        const int cnt = min(32, end - i);
        #pragma unroll 4
        for (int j = 0; j < cnt; j++) {
            const int   c  = __shfl_sync(0xffffffffu, my,  j);
            const float dc = SCALE_NBR ? __shfl_sync(0xffffffffu, myd, j) : 1.0f;
            const float4* src = reinterpret_cast<const float4*>(hs + (size_t)c * F);
            #pragma unroll
            for (int s = 0; s < NSEG; s++) {
                const float4 v = __ldg(&src[lane + 32 * s]);
                if (SCALE_NBR) {
                    acc[s].x = fmaf(dc, v.x, acc[s].x);
                    acc[s].y = fmaf(dc, v.y, acc[s].y);
                    acc[s].z = fmaf(dc, v.z, acc[s].z);
                    acc[s].w = fmaf(dc, v.w, acc[s].w);
                } else {
                    acc[s].x += v.x; acc[s].y += v.y;
                    acc[s].z += v.z; acc[s].w += v.w;
                }
            }
        }
    }

    float4* dst = reinterpret_cast<float4*>(outp + (size_t)node * F);
    const float4* bp = reinterpret_cast<const float4*>(bias);
    #pragma unroll
    for (int s = 0; s < NSEG; s++) {
        const float4 bv = __ldg(&bp[lane + 32 * s]);
        float4 v;
        v.x = fmaf(d, acc[s].x, bv.x);
        v.y = fmaf(d, acc[s].y, bv.y);
        v.z = fmaf(d, acc[s].z, bv.z);
        v.w = fmaf(d, acc[s].w, bv.w);
        if (RELU) {
            v.x = fmaxf(v.x, 0.f); v.y = fmaxf(v.y, 0.f);
            v.z = fmaxf(v.z, 0.f); v.w = fmaxf(v.w, 0.f);
        }
        dst[lane + 32 * s] = v;
    }
}

// -------- static side stream for CSR/GEMM1 overlap (created pre-capture) ----
static cudaStream_t g_s2 = nullptr;
static cudaEvent_t  g_evFork = nullptr, g_evJoin = nullptr;
static bool g_streams_ok = false;
namespace {
struct StreamInit {
    StreamInit() {
        g_streams_ok =
            cudaStreamCreateWithFlags(&g_s2, cudaStreamNonBlocking) == cudaSuccess &&
            cudaEventCreateWithFlags(&g_evFork, cudaEventDisableTiming) == cudaSuccess &&
            cudaEventCreateWithFlags(&g_evJoin, cudaEventDisableTiming) == cudaSuccess;
    }
} g_stream_init;
}

// ---------------------------------------------------------------
extern "C" void kernel_launch(void* const* d_in, const int* in_sizes, int n_in,
                              void* d_out, int out_size) {
    const float* x     = (const float*)d_in[0];
    const void*  edges = d_in[1];
    const float* W1    = (const float*)d_in[2];
    const float* b1    = (const float*)d_in[3];
    const float* W2    = (const float*)d_in[4];
    const float* b2    = (const float*)d_in[5];
    float* out = (float*)d_out;

    const int M = in_sizes[0] / F_IN;
    const int E = in_sizes[1] / 2;
    const int NB = (M + 255) / 256;

    float* h1   = nullptr;  cudaGetSymbolAddress((void**)&h1,   g_h1);
    float* agg1 = nullptr;  cudaGetSymbolAddress((void**)&agg1, g_agg1);
    float* h2   = nullptr;  cudaGetSymbolAddress((void**)&h2,   g_h2);

    cudaFuncSetAttribute(mma_gemm_kernel<false>,
                         cudaFuncAttributeMaxDynamicSharedMemorySize, GEMM_SMEM);
    cudaFuncSetAttribute(mma_gemm_kernel<true>,
                         cudaFuncAttributeMaxDynamicSharedMemorySize, GEMM_SMEM);

    // 0) edge dtype detection (both branches depend on it)
    {
        int nwords = 2 * E;
        if (nwords > 4096) nwords = 4096;
        detect_dtype_kernel<<<1, 256>>>((const unsigned int*)edges, nwords);
    }

    const dim3 grid1(F_HID / BN, (M + BM - 1) / BM);
    const dim3 grid2(F_OUT / BN, (M + BM - 1) / BM);
    const int eb = (E + 255) / 256;

    if (g_streams_ok) {
        // fork: CSR build on side stream, GEMM1 (dinv-free) on main stream
        cudaEventRecord(g_evFork, 0);
        cudaStreamWaitEvent(g_s2, g_evFork, 0);

        init_indeg_kernel<<<NB, 256, 0, g_s2>>>(M);
        indeg_kernel<<<eb, 256, 0, g_s2>>>(edges, E);
        scanA_kernel<<<NB, 256, 0, g_s2>>>(M);
        scanB_kernel<<<1, 256, 0, g_s2>>>(NB);
        scanC_kernel<<<NB, 256, 0, g_s2>>>(M);
        fill_kernel<<<eb, 256, 0, g_s2>>>(edges, E);
        cudaEventRecord(g_evJoin, g_s2);

        mma_gemm_kernel<false><<<grid1, 256, GEMM_SMEM>>>(x, W1, h1, M, F_HID, F_IN);

        cudaStreamWaitEvent(0, g_evJoin, 0);
    } else {
        init_indeg_kernel<<<NB, 256>>>(M);
        indeg_kernel<<<eb, 256>>>(edges, E);
        scanA_kernel<<<NB, 256>>>(M);
        scanB_kernel<<<1, 256>>>(NB);
        scanC_kernel<<<NB, 256>>>(M);
        fill_kernel<<<eb, 256>>>(edges, E);
        mma_gemm_kernel<false><<<grid1, 256, GEMM_SMEM>>>(x, W1, h1, M, F_HID, F_IN);
    }

    // gather1: agg1[r] = relu(dinv[r]*(dinv[r]*h1[r] + sum dinv[c]*h1[c]) + b1)
    {
        const long long threads = (long long)M * 32;
        gather_kernel<F_HID, true, true><<<(int)((threads + 255) / 256), 256>>>(h1, b1, agg1, M);
    }

    // GEMM2: hs2 = (agg1 @ W2) * dinv[row]
    mma_gemm_kernel<true><<<grid2, 256, GEMM_SMEM>>>(agg1, W2, h2, M, F_OUT, F_HID);

    // gather2: out[r] = dinv[r]*(hs2[r] + sum hs2[c]) + b2
    {
        const long long threads = (long long)M * 32;
        gather_kernel<F_OUT, false, false><<<(int)((threads + 255) / 256), 256>>>(h2, b2, out, M);
    }
}

// round 7
// speedup vs baseline: 4.1283x; 1.0546x over previous
#include <cuda_runtime.h>
#include <cuda_fp16.h>
#include <cstdint>

// GCN: out2 = GCNagg(relu(GCNagg(x@W1) + b1) @ W2) + b2
// R7: intermediate features h1/h2 stored fp16 (accumulation fp32 throughout);
//     CSR build overlapped with GEMM1; double-buffered tf32 mma.sync GEMM.

#define N_NODES 50000
#define F_IN    256
#define F_HID   256
#define F_OUT   128
#define MAX_E   320000

// -------- scratch (device globals; no allocations allowed) --------
__device__ __align__(16) __half g_h1f [(size_t)N_NODES * F_HID];  // x@W1 (raw, fp16)
__device__ __align__(16) float  g_agg1[(size_t)N_NODES * F_HID];  // layer-2 input (fp32)
__device__ __align__(16) __half g_h2f [(size_t)N_NODES * F_OUT];  // (agg1@W2)*dinv (fp16)
__device__ float g_dinv  [N_NODES];
__device__ int   g_indeg [N_NODES];
__device__ int   g_off   [N_NODES + 1];
__device__ int   g_cursor[N_NODES];
__device__ int   g_bsum  [256];
__device__ int   g_elist [MAX_E];
__device__ int   g_is64;

// ======================= tf32 warp-MMA GEMM (double-buffered) ===============
__device__ __forceinline__ uint32_t f2tf32(float f) {
    uint32_t u;
    asm("cvt.rn.tf32.f32 %0, %1;" : "=r"(u) : "f"(f));
    return u;
}

__device__ __forceinline__ void mma_16x8x8(float* c, const uint32_t* a, const uint32_t* b) {
    asm volatile(
        "mma.sync.aligned.m16n8k8.row.col.f32.tf32.tf32.f32 "
        "{%0,%1,%2,%3}, {%4,%5,%6,%7}, {%8,%9}, {%0,%1,%2,%3};"
        : "+f"(c[0]), "+f"(c[1]), "+f"(c[2]), "+f"(c[3])
        : "r"(a[0]), "r"(a[1]), "r"(a[2]), "r"(a[3]), "r"(b[0]), "r"(b[1]));
}

static constexpr int BM = 128, BN = 128, BK = 32;
static constexpr int APAD = 36;   // 36 % 32 == 4  -> a-frag banks 4g+t (distinct)
static constexpr int BPAD = 136;  // 136 % 32 == 8 -> b-frag banks 8t+g (distinct)
static constexpr int ASZ = BM * APAD;
static constexpr int BSZ = BK * BPAD;
static constexpr int STAGE = ASZ + BSZ;
static constexpr int GEMM_SMEM = 2 * STAGE * 4;  // ~70KB

// C is fp16; SCALE_EPI multiplies rows by dinv[row] before the convert.
template <bool SCALE_EPI>
__global__ __launch_bounds__(256)
void mma_gemm_kernel(const float* __restrict__ A,
                     const float* __restrict__ B,
                     __half* __restrict__ C16,
                     int M, int N, int K) {
    extern __shared__ uint32_t smem[];

    const int tid  = threadIdx.x;
    const int wid  = tid >> 5;
    const int lane = tid & 31;
    const int g    = lane >> 2;
    const int t    = lane & 3;
    const int wrow = (wid >> 2) * 64;
    const int wcol = (wid & 3) * 32;
    const int rowBase = blockIdx.y * BM;
    const int colBase = blockIdx.x * BN;

    float4 a_stage[4], b_stage[4];

    auto load_stage = [&](int k0) {
        #pragma unroll
        for (int it = 0; it < 4; it++) {
            const int idx = tid + it * 256;
            const int r  = idx >> 3;
            const int c4 = (idx & 7) * 4;
            const int gr = rowBase + r;
            a_stage[it] = (gr < M)
                ? *reinterpret_cast<const float4*>(A + (size_t)gr * K + k0 + c4)
                : make_float4(0.f, 0.f, 0.f, 0.f);
        }
        #pragma unroll
        for (int it = 0; it < 4; it++) {
            const int idx = tid + it * 256;
            const int r  = idx >> 5;
            const int c4 = (idx & 31) * 4;
            b_stage[it] = *reinterpret_cast<const float4*>(
                B + (size_t)(k0 + r) * N + colBase + c4);
        }
    };

    auto store_stage = [&](uint32_t* As, uint32_t* Bs) {
        #pragma unroll
        for (int it = 0; it < 4; it++) {
            const int idx = tid + it * 256;
            const int r  = idx >> 3;
            const int c4 = (idx & 7) * 4;
            uint4 tv;
            tv.x = f2tf32(a_stage[it].x); tv.y = f2tf32(a_stage[it].y);
            tv.z = f2tf32(a_stage[it].z); tv.w = f2tf32(a_stage[it].w);
            *reinterpret_cast<uint4*>(&As[r * APAD + c4]) = tv;
        }
        #pragma unroll
        for (int it = 0; it < 4; it++) {
            const int idx = tid + it * 256;
            const int r  = idx >> 5;
            const int c4 = (idx & 31) * 4;
            uint4 tv;
            tv.x = f2tf32(b_stage[it].x); tv.y = f2tf32(b_stage[it].y);
            tv.z = f2tf32(b_stage[it].z); tv.w = f2tf32(b_stage[it].w);
            *reinterpret_cast<uint4*>(&Bs[r * BPAD + c4]) = tv;
        }
    };

    float acc[4][4][4];
    #pragma unroll
    for (int i = 0; i < 4; i++)
        #pragma unroll
        for (int j = 0; j < 4; j++)
            #pragma unroll
            for (int c = 0; c < 4; c++) acc[i][j][c] = 0.0f;

    load_stage(0);

    const int ntiles = K / BK;
    for (int it = 0; it < ntiles; it++) {
        uint32_t* As = smem + (it & 1) * STAGE;
        uint32_t* Bs = As + ASZ;

        store_stage(As, Bs);
        __syncthreads();
        if (it + 1 < ntiles) load_stage((it + 1) * BK);

        #pragma unroll
        for (int ks = 0; ks < BK / 8; ks++) {
            const int kk = ks * 8;
            uint32_t afrag[4][4], bfrag[4][2];
            #pragma unroll
            for (int i = 0; i < 4; i++) {
                const int rb = wrow + i * 16;
                afrag[i][0] = As[(rb + g    ) * APAD + kk + t    ];
                afrag[i][1] = As[(rb + g + 8) * APAD + kk + t    ];
                afrag[i][2] = As[(rb + g    ) * APAD + kk + t + 4];
                afrag[i][3] = As[(rb + g + 8) * APAD + kk + t + 4];
            }
            #pragma unroll
            for (int j = 0; j < 4; j++) {
                const int nb = wcol + j * 8;
                bfrag[j][0] = Bs[(kk + t    ) * BPAD + nb + g];
                bfrag[j][1] = Bs[(kk + t + 4) * BPAD + nb + g];
            }
            #pragma unroll
            for (int i = 0; i < 4; i++)
                #pragma unroll
                for (int j = 0; j < 4; j++)
                    mma_16x8x8(acc[i][j], afrag[i], bfrag[j]);
        }
    }

    // ---- epilogue: optional dinv scale, convert to fp16, store __half2 ----
    #pragma unroll
    for (int i = 0; i < 4; i++) {
        #pragma unroll
        for (int half = 0; half < 2; half++) {
            const int gr = rowBase + wrow + i * 16 + g + half * 8;
            if (gr < M) {
                const float d = SCALE_EPI ? g_dinv[gr] : 1.0f;
                __half* dst = C16 + (size_t)gr * N + colBase + wcol;
                #pragma unroll
                for (int j = 0; j < 4; j++) {
                    const __half2 hv = __floats2half2_rn(acc[i][j][half * 2] * d,
                                                         acc[i][j][half * 2 + 1] * d);
                    *reinterpret_cast<__half2*>(dst + j * 8 + 2 * t) = hv;
                }
            }
        }
    }
}

// ======================= graph-side kernels =================================
__global__ void detect_dtype_kernel(const unsigned int* __restrict__ w, int nwords) {
    __shared__ unsigned int s_or;
    if (threadIdx.x == 0) s_or = 0u;
    __syncthreads();
    unsigned int v = 0u;
    for (int i = 2 * threadIdx.x + 1; i < nwords; i += 2 * blockDim.x) v |= w[i];
    atomicOr(&s_or, v);
    __syncthreads();
    if (threadIdx.x == 0) g_is64 = (s_or == 0u) ? 1 : 0;
}

__device__ __forceinline__ long long edge_get(const void* p, long long i) {
    return g_is64 ? ((const long long*)p)[i] : (long long)((const int*)p)[i];
}

__global__ void init_indeg_kernel(int n) {
    int i = blockIdx.x * blockDim.x + threadIdx.x;
    if (i < n) g_indeg[i] = 0;
}

__global__ void indeg_kernel(const void* __restrict__ edges, int E) {
    int e = blockIdx.x * blockDim.x + threadIdx.x;
    if (e < E) atomicAdd(&g_indeg[(int)edge_get(edges, e)], 1);
}

__global__ void scanA_kernel(int n) {
    __shared__ int s[256];
    const int t = threadIdx.x;
    const int i = blockIdx.x * 256 + t;
    int v = 0;
    if (i < n) {
        v = g_indeg[i];
        g_dinv[i] = rsqrtf((float)(v + 1));
    }
    s[t] = v;
    __syncthreads();
    #pragma unroll
    for (int off = 1; off < 256; off <<= 1) {
        int x = (t >= off) ? s[t - off] : 0;
        __syncthreads();
        s[t] += x;
        __syncthreads();
    }
    if (i < n) g_off[i + 1] = s[t];
    if (t == 255) g_bsum[blockIdx.x] = s[255];
}

__global__ void scanB_kernel(int nb) {
    __shared__ int s[256];
    const int t = threadIdx.x;
    s[t] = (t < nb) ? g_bsum[t] : 0;
    __syncthreads();
    #pragma unroll
    for (int off = 1; off < 256; off <<= 1) {
        int x = (t >= off) ? s[t - off] : 0;
        __syncthreads();
        s[t] += x;
        __syncthreads();
    }
    if (t < nb) g_bsum[t] = s[t];
}

__global__ void scanC_kernel(int n) {
    int i = blockIdx.x * blockDim.x + threadIdx.x;
    if (i >= n) return;
    const int b = i >> 8;
    const int add = (b > 0) ? g_bsum[b - 1] : 0;
    const int fin = g_off[i + 1] + add;
    g_off[i + 1] = fin;
    if (i + 1 < n) g_cursor[i + 1] = fin;
    if (i == 0) { g_off[0] = 0; g_cursor[0] = 0; }
}

__global__ void fill_kernel(const void* __restrict__ edges, int E) {
    int e = blockIdx.x * blockDim.x + threadIdx.x;
    if (e >= E) return;
    const int r = (int)edge_get(edges, e);
    const int c = (int)edge_get(edges, (long long)E + e);
    const int slot = atomicAdd(&g_cursor[r], 1);
    g_elist[slot] = c;
}

// ---- gather aggregation: warp per destination, fp16 source, fp32 accum ----
// SCALE_NBR=1: out[r] = post(dinv[r]*(dinv[r]*h[r] + sum dinv[c]*h[c]) + bias)
// SCALE_NBR=0: out[r] = post(dinv[r]*(hs[r] + sum hs[c]) + bias)   (hs pre-scaled)
template <int F, bool RELU, bool SCALE_NBR>
__global__ void gather_kernel(const __half* __restrict__ hf,
                              const float* __restrict__ bias,
                              float* __restrict__ outp,
                              int M) {
    const int node = (int)((blockIdx.x * blockDim.x + threadIdx.x) >> 5);
    const int lane = threadIdx.x & 31;
    if (node >= M) return;
    constexpr int CH = F / 32;   // halves per lane: 8 (F=256) or 4 (F=128)

    const float d = g_dinv[node];
    const float selfs = SCALE_NBR ? d : 1.0f;

    float acc[CH];
    // self term
    {
        const size_t base = (size_t)node * F + lane * CH;
        if (CH == 8) {
            const uint4 raw = __ldg(reinterpret_cast<const uint4*>(hf + base));
            const __half2* hp = reinterpret_cast<const __half2*>(&raw);
            #pragma unroll
            for (int k = 0; k < 4; k++) {
                const float2 f = __half22float2(hp[k]);
                acc[2 * k]     = selfs * f.x;
                acc[2 * k + 1] = selfs * f.y;
            }
        } else {
            const uint2 raw = __ldg(reinterpret_cast<const uint2*>(hf + base));
            const __half2* hp = reinterpret_cast<const __half2*>(&raw);
            #pragma unroll
            for (int k = 0; k < 2; k++) {
                const float2 f = __half22float2(hp[k]);
                acc[2 * k]     = selfs * f.x;
                acc[2 * k + 1] = selfs * f.y;
            }
        }
    }

    const int beg = g_off[node];
    const int end = g_off[node + 1];
    for (int i = beg; i < end; i += 32) {
        const int   my  = (i + lane < end) ? g_elist[i + lane] : 0;
        const float myd = SCALE_NBR ? g_dinv[my] : 1.0f;
        const int cnt = min(32, end - i);
        #pragma unroll 4
        for (int j = 0; j < cnt; j++) {
            const int   c  = __shfl_sync(0xffffffffu, my,  j);
            const float dc = SCALE_NBR ? __shfl_sync(0xffffffffu, myd, j) : 1.0f;
            const size_t base = (size_t)c * F + lane * CH;
            if (CH == 8) {
                const uint4 raw = __ldg(reinterpret_cast<const uint4*>(hf + base));
                const __half2* hp = reinterpret_cast<const __half2*>(&raw);
                #pragma unroll
                for (int k = 0; k < 4; k++) {
                    const float2 f = __half22float2(hp[k]);
                    if (SCALE_NBR) {
                        acc[2 * k]     = fmaf(dc, f.x, acc[2 * k]);
                        acc[2 * k + 1] = fmaf(dc, f.y, acc[2 * k + 1]);
                    } else {
                        acc[2 * k]     += f.x;
                        acc[2 * k + 1] += f.y;
                    }
                }
            } else {
                const uint2 raw = __ldg(reinterpret_cast<const uint2*>(hf + base));
                const __half2* hp = reinterpret_cast<const __half2*>(&raw);
                #pragma unroll
                for (int k = 0; k < 2; k++) {
                    const float2 f = __half22float2(hp[k]);
                    if (SCALE_NBR) {
                        acc[2 * k]     = fmaf(dc, f.x, acc[2 * k]);
                        acc[2 * k + 1] = fmaf(dc, f.y, acc[2 * k + 1]);
                    } else {
                        acc[2 * k]     += f.x;
                        acc[2 * k + 1] += f.y;
                    }
                }
            }
        }
    }

    // epilogue: v = dinv[node]*acc + bias  (+relu); contiguous per-lane chunk
    float* dst = outp + (size_t)node * F + lane * CH;
    const float* bp = bias + lane * CH;
    #pragma unroll
    for (int k = 0; k < CH; k += 4) {
        const float4 bv = __ldg(reinterpret_cast<const float4*>(bp + k));
        float4 v;
        v.x = fmaf(d, acc[k + 0], bv.x);
        v.y = fmaf(d, acc[k + 1], bv.y);
        v.z = fmaf(d, acc[k + 2], bv.z);
        v.w = fmaf(d, acc[k + 3], bv.w);
        if (RELU) {
            v.x = fmaxf(v.x, 0.f); v.y = fmaxf(v.y, 0.f);
            v.z = fmaxf(v.z, 0.f); v.w = fmaxf(v.w, 0.f);
        }
        *reinterpret_cast<float4*>(dst + k) = v;
    }
}

// -------- static side stream for CSR/GEMM1 overlap (created pre-capture) ----
static cudaStream_t g_s2 = nullptr;
static cudaEvent_t  g_evFork = nullptr, g_evJoin = nullptr;
static bool g_streams_ok = false;
namespace {
struct StreamInit {
    StreamInit() {
        g_streams_ok =
            cudaStreamCreateWithFlags(&g_s2, cudaStreamNonBlocking) == cudaSuccess &&
            cudaEventCreateWithFlags(&g_evFork, cudaEventDisableTiming) == cudaSuccess &&
            cudaEventCreateWithFlags(&g_evJoin, cudaEventDisableTiming) == cudaSuccess;
    }
} g_stream_init;
}

// ---------------------------------------------------------------
extern "C" void kernel_launch(void* const* d_in, const int* in_sizes, int n_in,
                              void* d_out, int out_size) {
    const float* x     = (const float*)d_in[0];
    const void*  edges = d_in[1];
    const float* W1    = (const float*)d_in[2];
    const float* b1    = (const float*)d_in[3];
    const float* W2    = (const float*)d_in[4];
    const float* b2    = (const float*)d_in[5];
    float* out = (float*)d_out;

    const int M = in_sizes[0] / F_IN;
    const int E = in_sizes[1] / 2;
    const int NB = (M + 255) / 256;

    __half* h1f  = nullptr;  cudaGetSymbolAddress((void**)&h1f,  g_h1f);
    float*  agg1 = nullptr;  cudaGetSymbolAddress((void**)&agg1, g_agg1);
    __half* h2f  = nullptr;  cudaGetSymbolAddress((void**)&h2f,  g_h2f);

    cudaFuncSetAttribute(mma_gemm_kernel<false>,
                         cudaFuncAttributeMaxDynamicSharedMemorySize, GEMM_SMEM);
    cudaFuncSetAttribute(mma_gemm_kernel<true>,
                         cudaFuncAttributeMaxDynamicSharedMemorySize, GEMM_SMEM);

    // 0) edge dtype detection (both branches depend on it)
    {
        int nwords = 2 * E;
        if (nwords > 4096) nwords = 4096;
        detect_dtype_kernel<<<1, 256>>>((const unsigned int*)edges, nwords);
    }

    const dim3 grid1(F_HID / BN, (M + BM - 1) / BM);
    const dim3 grid2(F_OUT / BN, (M + BM - 1) / BM);
    const int eb = (E + 255) / 256;

    if (g_streams_ok) {
        cudaEventRecord(g_evFork, 0);
        cudaStreamWaitEvent(g_s2, g_evFork, 0);

        init_indeg_kernel<<<NB, 256, 0, g_s2>>>(M);
        indeg_kernel<<<eb, 256, 0, g_s2>>>(edges, E);
        scanA_kernel<<<NB, 256, 0, g_s2>>>(M);
        scanB_kernel<<<1, 256, 0, g_s2>>>(NB);
        scanC_kernel<<<NB, 256, 0, g_s2>>>(M);
        fill_kernel<<<eb, 256, 0, g_s2>>>(edges, E);
        cudaEventRecord(g_evJoin, g_s2);

        mma_gemm_kernel<false><<<grid1, 256, GEMM_SMEM>>>(x, W1, h1f, M, F_HID, F_IN);

        cudaStreamWaitEvent(0, g_evJoin, 0);
    } else {
        init_indeg_kernel<<<NB, 256>>>(M);
        indeg_kernel<<<eb, 256>>>(edges, E);
        scanA_kernel<<<NB, 256>>>(M);
        scanB_kernel<<<1, 256>>>(NB);
        scanC_kernel<<<NB, 256>>>(M);
        fill_kernel<<<eb, 256>>>(edges, E);
        mma_gemm_kernel<false><<<grid1, 256, GEMM_SMEM>>>(x, W1, h1f, M, F_HID, F_IN);
    }

    // gather1: agg1[r] = relu(dinv[r]*(dinv[r]*h1[r] + sum dinv[c]*h1[c]) + b1)
    {
        const long long threads = (long long)M * 32;
        gather_kernel<F_HID, true, true><<<(int)((threads + 255) / 256), 256>>>(h1f, b1, agg1, M);
    }

    // GEMM2: hs2 = (agg1 @ W2) * dinv[row]  -> fp16
    mma_gemm_kernel<true><<<grid2, 256, GEMM_SMEM>>>(agg1, W2, h2f, M, F_OUT, F_HID);

    // gather2: out[r] = dinv[r]*(hs2[r] + sum hs2[c]) + b2
    {
        const long long threads = (long long)M * 32;
        gather_kernel<F_OUT, false, false><<<(int)((threads + 255) / 256), 256>>>(h2f, b2, out, M);
    }
}

// round 9
// speedup vs baseline: 4.5158x; 1.0939x over previous
#include <cuda_runtime.h>
#include <cuda_fp16.h>
#include <cstdint>

// GCN: out2 = GCNagg(relu(GCNagg(x@W1) + b1) @ W2) + b2
// R9 (= R8 resubmit after infra failure): fp16 m16n8k16 tensor-core GEMMs
// (fp32 accum) with pre-transposed fp16 weights; agg1 stored fp16;
// 2-warps-per-node gather for F=256; CSR build overlapped with GEMM1.

#define N_NODES 50000
#define F_IN    256
#define F_HID   256
#define F_OUT   128
#define MAX_E   320000

// -------- scratch (device globals; no allocations allowed) --------
__device__ __align__(16) __half g_h1f [(size_t)N_NODES * F_HID];  // x@W1 (raw fp16)
__device__ __align__(16) __half g_agg1[(size_t)N_NODES * F_HID];  // layer-2 input fp16
__device__ __align__(16) __half g_h2f [(size_t)N_NODES * F_OUT];  // (agg1@W2)*dinv fp16
__device__ __align__(16) __half g_w1t [(size_t)F_IN  * F_HID];    // W1^T fp16 [N][K]
__device__ __align__(16) __half g_w2t [(size_t)F_HID * F_OUT];    // W2^T fp16 [N][K]
__device__ float g_dinv  [N_NODES];
__device__ int   g_indeg [N_NODES];
__device__ int   g_off   [N_NODES + 1];
__device__ int   g_cursor[N_NODES];
__device__ int   g_bsum  [256];
__device__ int   g_elist [MAX_E];
__device__ int   g_is64;

// ======================= fp16 warp-MMA GEMM (double-buffered) ===============
// C[M,N] = A[M,K] @ W^T[N,K]^T.  BM=BN=128, BK=32, 256 threads (8 warps 2x4),
// warp tile 64x32 of m16n8k16. Smem rows stride 40 halves (conflict-free
// fragment reads; 80B row pitch keeps uint4 stores 16B-aligned).

__device__ __forceinline__ void mma_16x8x16(float* c, const uint32_t* a, const uint32_t* b) {
    asm volatile(
        "mma.sync.aligned.m16n8k16.row.col.f32.f16.f16.f32 "
        "{%0,%1,%2,%3}, {%4,%5,%6,%7}, {%8,%9}, {%0,%1,%2,%3};"
        : "+f"(c[0]), "+f"(c[1]), "+f"(c[2]), "+f"(c[3])
        : "r"(a[0]), "r"(a[1]), "r"(a[2]), "r"(a[3]), "r"(b[0]), "r"(b[1]));
}

static constexpr int BM = 128, BN = 128, BK = 32;
static constexpr int LDT = 40;                   // smem row stride in halves
static constexpr int ASZ = BM * LDT;             // halves
static constexpr int BSZ = BN * LDT;             // halves ([n][k] tile)
static constexpr int STAGE = ASZ + BSZ;          // halves per buffer
static constexpr int GEMM_SMEM = 2 * STAGE * 2;  // bytes (~40KB)

template <bool A_HALF, bool SCALE_EPI>
__global__ __launch_bounds__(256)
void mma_gemm_fp16(const void* __restrict__ Aptr,
                   const __half* __restrict__ BT,   // [N][K] fp16
                   __half* __restrict__ C16,
                   int M, int N, int K) {
    extern __shared__ __half smemh[];

    const int tid  = threadIdx.x;
    const int wid  = tid >> 5;
    const int lane = tid & 31;
    const int g    = lane >> 2;
    const int t    = lane & 3;
    const int wrow = (wid >> 2) * 64;
    const int wcol = (wid & 3) * 32;
    const int rowBase = blockIdx.y * BM;
    const int colBase = blockIdx.x * BN;

    float4 a_stf[4];   // A fp32 staging
    uint4  a_sth[2];   // A fp16 staging
    uint4  b_st[2];    // B fp16 staging

    auto load_stage = [&](int k0) {
        if (A_HALF) {
            const __half* Ah = (const __half*)Aptr;
            #pragma unroll
            for (int it = 0; it < 2; it++) {
                const int idx = tid + it * 256;
                const int r  = idx >> 2;
                const int c8 = (idx & 3) * 8;
                const int gr = rowBase + r;
                a_sth[it] = (gr < M)
                    ? *reinterpret_cast<const uint4*>(Ah + (size_t)gr * K + k0 + c8)
                    : make_uint4(0u, 0u, 0u, 0u);
            }
        } else {
            const float* Af = (const float*)Aptr;
            #pragma unroll
            for (int it = 0; it < 4; it++) {
                const int idx = tid + it * 256;
                const int r  = idx >> 3;
                const int c4 = (idx & 7) * 4;
                const int gr = rowBase + r;
                a_stf[it] = (gr < M)
                    ? *reinterpret_cast<const float4*>(Af + (size_t)gr * K + k0 + c4)
                    : make_float4(0.f, 0.f, 0.f, 0.f);
            }
        }
        #pragma unroll
        for (int it = 0; it < 2; it++) {
            const int idx = tid + it * 256;
            const int n  = idx >> 2;
            const int c8 = (idx & 3) * 8;
            b_st[it] = *reinterpret_cast<const uint4*>(
                BT + (size_t)(colBase + n) * K + k0 + c8);
        }
    };

    auto store_stage = [&](__half* As, __half* Bs) {
        if (A_HALF) {
            #pragma unroll
            for (int it = 0; it < 2; it++) {
                const int idx = tid + it * 256;
                const int r  = idx >> 2;
                const int c8 = (idx & 3) * 8;
                *reinterpret_cast<uint4*>(As + r * LDT + c8) = a_sth[it];
            }
        } else {
            #pragma unroll
            for (int it = 0; it < 4; it++) {
                const int idx = tid + it * 256;
                const int r  = idx >> 3;
                const int c4 = (idx & 7) * 4;
                const __half2 h01 = __floats2half2_rn(a_stf[it].x, a_stf[it].y);
                const __half2 h23 = __floats2half2_rn(a_stf[it].z, a_stf[it].w);
                uint2 u;
                u.x = *reinterpret_cast<const uint32_t*>(&h01);
                u.y = *reinterpret_cast<const uint32_t*>(&h23);
                *reinterpret_cast<uint2*>(As + r * LDT + c4) = u;
            }
        }
        #pragma unroll
        for (int it = 0; it < 2; it++) {
            const int idx = tid + it * 256;
            const int n  = idx >> 2;
            const int c8 = (idx & 3) * 8;
            *reinterpret_cast<uint4*>(Bs + n * LDT + c8) = b_st[it];
        }
    };

    float acc[4][4][4];
    #pragma unroll
    for (int i = 0; i < 4; i++)
        #pragma unroll
        for (int j = 0; j < 4; j++)
            #pragma unroll
            for (int c = 0; c < 4; c++) acc[i][j][c] = 0.0f;

    load_stage(0);

    const int ntiles = K / BK;
    for (int it = 0; it < ntiles; it++) {
        __half* As = smemh + (it & 1) * STAGE;
        __half* Bs = As + ASZ;

        store_stage(As, Bs);
        __syncthreads();
        if (it + 1 < ntiles) load_stage((it + 1) * BK);

        #pragma unroll
        for (int ks = 0; ks < 2; ks++) {           // two k=16 steps
            const int kk = ks * 16;
            uint32_t af[4][4], bf[4][2];
            #pragma unroll
            for (int i = 0; i < 4; i++) {
                const int rb = wrow + i * 16;
                af[i][0] = *reinterpret_cast<const uint32_t*>(&As[(rb + g    ) * LDT + kk + 2 * t    ]);
                af[i][1] = *reinterpret_cast<const uint32_t*>(&As[(rb + g + 8) * LDT + kk + 2 * t    ]);
                af[i][2] = *reinterpret_cast<const uint32_t*>(&As[(rb + g    ) * LDT + kk + 2 * t + 8]);
                af[i][3] = *reinterpret_cast<const uint32_t*>(&As[(rb + g + 8) * LDT + kk + 2 * t + 8]);
            }
            #pragma unroll
            for (int j = 0; j < 4; j++) {
                const int nb = wcol + j * 8;
                bf[j][0] = *reinterpret_cast<const uint32_t*>(&Bs[(nb + g) * LDT + kk + 2 * t    ]);
                bf[j][1] = *reinterpret_cast<const uint32_t*>(&Bs[(nb + g) * LDT + kk + 2 * t + 8]);
            }
            #pragma unroll
            for (int i = 0; i < 4; i++)
                #pragma unroll
                for (int j = 0; j < 4; j++)
                    mma_16x8x16(acc[i][j], af[i], bf[j]);
        }
    }

    // ---- epilogue: optional dinv scale, convert to fp16 ----
    #pragma unroll
    for (int i = 0; i < 4; i++) {
        #pragma unroll
        for (int half = 0; half < 2; half++) {
            const int gr = rowBase + wrow + i * 16 + g + half * 8;
            if (gr < M) {
                const float d = SCALE_EPI ? g_dinv[gr] : 1.0f;
                __half* dst = C16 + (size_t)gr * N + colBase + wcol;
                #pragma unroll
                for (int j = 0; j < 4; j++) {
                    const __half2 hv = __floats2half2_rn(acc[i][j][half * 2] * d,
                                                         acc[i][j][half * 2 + 1] * d);
                    *reinterpret_cast<__half2*>(dst + j * 8 + 2 * t) = hv;
                }
            }
        }
    }
}

// -------- weight transpose+convert: W[K][N] fp32 -> WT[N][K] fp16 -----------
__global__ void transpose_w_kernel(const float* __restrict__ W,
                                   __half* __restrict__ WT,
                                   int K, int N) {
    __shared__ float tile[32][33];
    const int k0 = blockIdx.y * 32;
    const int n0 = blockIdx.x * 32;
    const int tx = threadIdx.x, ty = threadIdx.y;   // 32 x 8
    #pragma unroll
    for (int i = 0; i < 32; i += 8)
        tile[ty + i][tx] = W[(size_t)(k0 + ty + i) * N + n0 + tx];
    __syncthreads();
    #pragma unroll
    for (int i = 0; i < 32; i += 8)
        WT[(size_t)(n0 + ty + i) * K + k0 + tx] = __float2half_rn(tile[tx][ty + i]);
}

// ======================= graph-side kernels =================================
__global__ void detect_dtype_kernel(const unsigned int* __restrict__ w, int nwords) {
    __shared__ unsigned int s_or;
    if (threadIdx.x == 0) s_or = 0u;
    __syncthreads();
    unsigned int v = 0u;
    for (int i = 2 * threadIdx.x + 1; i < nwords; i += 2 * blockDim.x) v |= w[i];
    atomicOr(&s_or, v);
    __syncthreads();
    if (threadIdx.x == 0) g_is64 = (s_or == 0u) ? 1 : 0;
}

__device__ __forceinline__ long long edge_get(const void* p, long long i) {
    return g_is64 ? ((const long long*)p)[i] : (long long)((const int*)p)[i];
}

__global__ void init_indeg_kernel(int n) {
    int i = blockIdx.x * blockDim.x + threadIdx.x;
    if (i < n) g_indeg[i] = 0;
}

__global__ void indeg_kernel(const void* __restrict__ edges, int E) {
    int e = blockIdx.x * blockDim.x + threadIdx.x;
    if (e < E) atomicAdd(&g_indeg[(int)edge_get(edges, e)], 1);
}

__global__ void scanA_kernel(int n) {
    __shared__ int s[256];
    const int t = threadIdx.x;
    const int i = blockIdx.x * 256 + t;
    int v = 0;
    if (i < n) {
        v = g_indeg[i];
        g_dinv[i] = rsqrtf((float)(v + 1));
    }
    s[t] = v;
    __syncthreads();
    #pragma unroll
    for (int off = 1; off < 256; off <<= 1) {
        int x = (t >= off) ? s[t - off] : 0;
        __syncthreads();
        s[t] += x;
        __syncthreads();
    }
    if (i < n) g_off[i + 1] = s[t];
    if (t == 255) g_bsum[blockIdx.x] = s[255];
}

__global__ void scanB_kernel(int nb) {
    __shared__ int s[256];
    const int t = threadIdx.x;
    s[t] = (t < nb) ? g_bsum[t] : 0;
    __syncthreads();
    #pragma unroll
    for (int off = 1; off < 256; off <<= 1) {
        int x = (t >= off) ? s[t - off] : 0;
        __syncthreads();
        s[t] += x;
        __syncthreads();
    }
    if (t < nb) g_bsum[t] = s[t];
}

__global__ void scanC_kernel(int n) {
    int i = blockIdx.x * blockDim.x + threadIdx.x;
    if (i >= n) return;
    const int b = i >> 8;
    const int add = (b > 0) ? g_bsum[b - 1] : 0;
    const int fin = g_off[i + 1] + add;
    g_off[i + 1] = fin;
    if (i + 1 < n) g_cursor[i + 1] = fin;
    if (i == 0) { g_off[0] = 0; g_cursor[0] = 0; }
}

__global__ void fill_kernel(const void* __restrict__ edges, int E) {
    int e = blockIdx.x * blockDim.x + threadIdx.x;
    if (e >= E) return;
    const int r = (int)edge_get(edges, e);
    const int c = (int)edge_get(edges, (long long)E + e);
    const int slot = atomicAdd(&g_cursor[r], 1);
    g_elist[slot] = c;
}

// ---- gather aggregation: SPLIT warps per destination node ------------------
// Each warp-unit handles F/SPLIT features (4 halves per lane).
// SCALE_NBR=1: out = post(dinv[r]*(dinv[r]*h[r] + sum dinv[c]*h[c]) + bias)
// SCALE_NBR=0: out = post(dinv[r]*(hs[r] + sum hs[c]) + bias)
template <int F, int SPLIT, bool RELU, bool SCALE_NBR, bool OUT_HALF>
__global__ void gather_kernel(const __half* __restrict__ hf,
                              const float* __restrict__ bias,
                              void* __restrict__ outp,
                              int M) {
    const int wunit = (int)((blockIdx.x * blockDim.x + threadIdx.x) >> 5);
    const int lane = threadIdx.x & 31;
    const int node = wunit / SPLIT;
    const int part = wunit - node * SPLIT;
    if (node >= M) return;
    const int fofs = part * (F / SPLIT) + lane * 4;

    const float d = g_dinv[node];
    const float selfs = SCALE_NBR ? d : 1.0f;

    float acc[4];
    {
        const uint2 raw = __ldg(reinterpret_cast<const uint2*>(hf + (size_t)node * F + fofs));
        const __half2* hp = reinterpret_cast<const __half2*>(&raw);
        const float2 f0 = __half22float2(hp[0]);
        const float2 f1 = __half22float2(hp[1]);
        acc[0] = selfs * f0.x; acc[1] = selfs * f0.y;
        acc[2] = selfs * f1.x; acc[3] = selfs * f1.y;
    }

    const int beg = g_off[node];
    const int end = g_off[node + 1];
    for (int i = beg; i < end; i += 32) {
        const int   my  = (i + lane < end) ? g_elist[i + lane] : 0;
        const float myd = SCALE_NBR ? g_dinv[my] : 1.0f;
        const int cnt = min(32, end - i);
        #pragma unroll 4
        for (int j = 0; j < cnt; j++) {
            const int   c  = __shfl_sync(0xffffffffu, my,  j);
            const float dc = SCALE_NBR ? __shfl_sync(0xffffffffu, myd, j) : 1.0f;
            const uint2 raw = __ldg(reinterpret_cast<const uint2*>(hf + (size_t)c * F + fofs));
            const __half2* hp = reinterpret_cast<const __half2*>(&raw);
            const float2 f0 = __half22float2(hp[0]);
            const float2 f1 = __half22float2(hp[1]);
            if (SCALE_NBR) {
                acc[0] = fmaf(dc, f0.x, acc[0]); acc[1] = fmaf(dc, f0.y, acc[1]);
                acc[2] = fmaf(dc, f1.x, acc[2]); acc[3] = fmaf(dc, f1.y, acc[3]);
            } else {
                acc[0] += f0.x; acc[1] += f0.y;
                acc[2] += f1.x; acc[3] += f1.y;
            }
        }
    }

    const float4 bv = __ldg(reinterpret_cast<const float4*>(bias + fofs));
    float4 v;
    v.x = fmaf(d, acc[0], bv.x);
    v.y = fmaf(d, acc[1], bv.y);
    v.z = fmaf(d, acc[2], bv.z);
    v.w = fmaf(d, acc[3], bv.w);
    if (RELU) {
        v.x = fmaxf(v.x, 0.f); v.y = fmaxf(v.y, 0.f);
        v.z = fmaxf(v.z, 0.f); v.w = fmaxf(v.w, 0.f);
    }
    if (OUT_HALF) {
        const __half2 h01 = __floats2half2_rn(v.x, v.y);
        const __half2 h23 = __floats2half2_rn(v.z, v.w);
        uint2 u;
        u.x = *reinterpret_cast<const uint32_t*>(&h01);
        u.y = *reinterpret_cast<const uint32_t*>(&h23);
        *reinterpret_cast<uint2*>((__half*)outp + (size_t)node * F + fofs) = u;
    } else {
        *reinterpret_cast<float4*>((float*)outp + (size_t)node * F + fofs) = v;
    }
}

// -------- static side stream for CSR/GEMM1 overlap (created pre-capture) ----
static cudaStream_t g_s2 = nullptr;
static cudaEvent_t  g_evFork = nullptr, g_evJoin = nullptr;
static bool g_streams_ok = false;
namespace {
struct StreamInit {
    StreamInit() {
        g_streams_ok =
            cudaStreamCreateWithFlags(&g_s2, cudaStreamNonBlocking) == cudaSuccess &&
            cudaEventCreateWithFlags(&g_evFork, cudaEventDisableTiming) == cudaSuccess &&
            cudaEventCreateWithFlags(&g_evJoin, cudaEventDisableTiming) == cudaSuccess;
    }
} g_stream_init;
}

// ---------------------------------------------------------------
extern "C" void kernel_launch(void* const* d_in, const int* in_sizes, int n_in,
                              void* d_out, int out_size) {
    const float* x     = (const float*)d_in[0];
    const void*  edges = d_in[1];
    const float* W1    = (const float*)d_in[2];
    const float* b1    = (const float*)d_in[3];
    const float* W2    = (const float*)d_in[4];
    const float* b2    = (const float*)d_in[5];
    float* out = (float*)d_out;

    const int M = in_sizes[0] / F_IN;
    const int E = in_sizes[1] / 2;
    const int NB = (M + 255) / 256;

    __half* h1f  = nullptr;  cudaGetSymbolAddress((void**)&h1f,  g_h1f);
    __half* agg1 = nullptr;  cudaGetSymbolAddress((void**)&agg1, g_agg1);
    __half* h2f  = nullptr;  cudaGetSymbolAddress((void**)&h2f,  g_h2f);
    __half* w1t  = nullptr;  cudaGetSymbolAddress((void**)&w1t,  g_w1t);
    __half* w2t  = nullptr;  cudaGetSymbolAddress((void**)&w2t,  g_w2t);

    // 0) edge dtype detection (CSR chain depends on it)
    {
        int nwords = 2 * E;
        if (nwords > 4096) nwords = 4096;
        detect_dtype_kernel<<<1, 256>>>((const unsigned int*)edges, nwords);
    }

    const dim3 grid1(F_HID / BN, (M + BM - 1) / BM);
    const dim3 grid2(F_OUT / BN, (M + BM - 1) / BM);
    const dim3 tblk(32, 8);
    const int eb = (E + 255) / 256;

    if (g_streams_ok) {
        cudaEventRecord(g_evFork, 0);
        cudaStreamWaitEvent(g_s2, g_evFork, 0);

        init_indeg_kernel<<<NB, 256, 0, g_s2>>>(M);
        indeg_kernel<<<eb, 256, 0, g_s2>>>(edges, E);
        scanA_kernel<<<NB, 256, 0, g_s2>>>(M);
        scanB_kernel<<<1, 256, 0, g_s2>>>(NB);
        scanC_kernel<<<NB, 256, 0, g_s2>>>(M);
        fill_kernel<<<eb, 256, 0, g_s2>>>(edges, E);
        cudaEventRecord(g_evJoin, g_s2);

        transpose_w_kernel<<<dim3(F_HID / 32, F_IN / 32), tblk>>>(W1, w1t, F_IN, F_HID);
        transpose_w_kernel<<<dim3(F_OUT / 32, F_HID / 32), tblk>>>(W2, w2t, F_HID, F_OUT);
        mma_gemm_fp16<false, false><<<grid1, 256, GEMM_SMEM>>>(x, w1t, h1f, M, F_HID, F_IN);

        cudaStreamWaitEvent(0, g_evJoin, 0);
    } else {
        init_indeg_kernel<<<NB, 256>>>(M);
        indeg_kernel<<<eb, 256>>>(edges, E);
        scanA_kernel<<<NB, 256>>>(M);
        scanB_kernel<<<1, 256>>>(NB);
        scanC_kernel<<<NB, 256>>>(M);
        fill_kernel<<<eb, 256>>>(edges, E);
        transpose_w_kernel<<<dim3(F_HID / 32, F_IN / 32), tblk>>>(W1, w1t, F_IN, F_HID);
        transpose_w_kernel<<<dim3(F_OUT / 32, F_HID / 32), tblk>>>(W2, w2t, F_HID, F_OUT);
        mma_gemm_fp16<false, false><<<grid1, 256, GEMM_SMEM>>>(x, w1t, h1f, M, F_HID, F_IN);
    }

    // gather1 (2 warps/node): agg1[r] = relu(dinv[r]*(dinv[r]*h1[r] + sum dinv[c]*h1[c]) + b1)
    {
        const long long warps = (long long)M * 2;
        gather_kernel<F_HID, 2, true, true, true>
            <<<(int)((warps * 32 + 255) / 256), 256>>>(h1f, b1, agg1, M);
    }

    // GEMM2: hs2 = (agg1 @ W2) * dinv[row]  (A fp16 direct)
    mma_gemm_fp16<true, true><<<grid2, 256, GEMM_SMEM>>>(agg1, w2t, h2f, M, F_OUT, F_HID);

    // gather2 (1 warp/node): out[r] = dinv[r]*(hs2[r] + sum hs2[c]) + b2
    {
        const long long warps = (long long)M;
        gather_kernel<F_OUT, 1, false, false, false>
            <<<(int)((warps * 32 + 255) / 256), 256>>>(h2f, b2, out, M);
    }
}

// round 10
// speedup vs baseline: 5.3971x; 1.1952x over previous
#include <cuda_runtime.h>
#include <cuda_fp16.h>
#include <cstdint>

// GCN: out2 = GCNagg(relu(GCNagg(x@W1) + b1) @ W2) + b2
// R10: ldmatrix.x4 fragment loads in the fp16 m16n8k16 GEMMs (12 ldmatrix vs
//      48 LDS per warp-tile); detect_dtype + W2-transpose moved off the
//      critical path onto the CSR side stream.

#define N_NODES 50000
#define F_IN    256
#define F_HID   256
#define F_OUT   128
#define MAX_E   320000

// -------- scratch (device globals; no allocations allowed) --------
__device__ __align__(16) __half g_h1f [(size_t)N_NODES * F_HID];  // x@W1 (raw fp16)
__device__ __align__(16) __half g_agg1[(size_t)N_NODES * F_HID];  // layer-2 input fp16
__device__ __align__(16) __half g_h2f [(size_t)N_NODES * F_OUT];  // (agg1@W2)*dinv fp16
__device__ __align__(16) __half g_w1t [(size_t)F_IN  * F_HID];    // W1^T fp16 [N][K]
__device__ __align__(16) __half g_w2t [(size_t)F_HID * F_OUT];    // W2^T fp16 [N][K]
__device__ float g_dinv  [N_NODES];
__device__ int   g_indeg [N_NODES];
__device__ int   g_off   [N_NODES + 1];
__device__ int   g_cursor[N_NODES];
__device__ int   g_bsum  [256];
__device__ int   g_elist [MAX_E];
__device__ int   g_is64;

// ======================= fp16 warp-MMA GEMM (double-buffered) ===============
// C[M,N] = A[M,K] @ W^T[N,K]^T.  BM=BN=128, BK=32, 256 threads (8 warps 2x4),
// warp tile 64x32 of m16n8k16. Fragment loads via ldmatrix.x4; 80B smem row
// pitch -> each 8-row ldmatrix phase covers all 32 banks once (conflict-free).

__device__ __forceinline__ void mma_16x8x16(float* c, const uint32_t* a, const uint32_t* b) {
    asm volatile(
        "mma.sync.aligned.m16n8k16.row.col.f32.f16.f16.f32 "
        "{%0,%1,%2,%3}, {%4,%5,%6,%7}, {%8,%9}, {%0,%1,%2,%3};"
        : "+f"(c[0]), "+f"(c[1]), "+f"(c[2]), "+f"(c[3])
        : "r"(a[0]), "r"(a[1]), "r"(a[2]), "r"(a[3]), "r"(b[0]), "r"(b[1]));
}

#define LDSM_X4(r0, r1, r2, r3, addr) \
    asm volatile("ldmatrix.sync.aligned.m8n8.x4.shared.b16 {%0,%1,%2,%3}, [%4];" \
                 : "=r"(r0), "=r"(r1), "=r"(r2), "=r"(r3) : "r"(addr))

static constexpr int BM = 128, BN = 128, BK = 32;
static constexpr int LDT = 40;                   // smem row stride in halves (80B)
static constexpr int ASZ = BM * LDT;
static constexpr int BSZ = BN * LDT;
static constexpr int STAGE = ASZ + BSZ;
static constexpr int GEMM_SMEM = 2 * STAGE * 2;  // ~40KB

template <bool A_HALF, bool SCALE_EPI>
__global__ __launch_bounds__(256)
void mma_gemm_fp16(const void* __restrict__ Aptr,
                   const __half* __restrict__ BT,   // [N][K] fp16
                   __half* __restrict__ C16,
                   int M, int N, int K) {
    extern __shared__ __half smemh[];

    const int tid  = threadIdx.x;
    const int wid  = tid >> 5;
    const int lane = tid & 31;
    const int g    = lane >> 2;
    const int t    = lane & 3;
    const int wrow = (wid >> 2) * 64;
    const int wcol = (wid & 3) * 32;
    const int rowBase = blockIdx.y * BM;
    const int colBase = blockIdx.x * BN;

    // ldmatrix per-lane address components
    const int a_r = lane & 15;            // row within 16-row tile
    const int a_c = (lane >> 4) * 8;      // k offset: tiles 2,3 at +8
    const int b_n = ((lane >> 4) << 3) + (lane & 7);  // n within 16-n pair
    const int b_k = ((lane >> 3) & 1) * 8;            // k offset per tile

    float4 a_stf[4];   // A fp32 staging
    uint4  a_sth[2];   // A fp16 staging
    uint4  b_st[2];    // B fp16 staging

    auto load_stage = [&](int k0) {
        if (A_HALF) {
            const __half* Ah = (const __half*)Aptr;
            #pragma unroll
            for (int it = 0; it < 2; it++) {
                const int idx = tid + it * 256;
                const int r  = idx >> 2;
                const int c8 = (idx & 3) * 8;
                const int gr = rowBase + r;
                a_sth[it] = (gr < M)
                    ? *reinterpret_cast<const uint4*>(Ah + (size_t)gr * K + k0 + c8)
                    : make_uint4(0u, 0u, 0u, 0u);
            }
        } else {
            const float* Af = (const float*)Aptr;
            #pragma unroll
            for (int it = 0; it < 4; it++) {
                const int idx = tid + it * 256;
                const int r  = idx >> 3;
                const int c4 = (idx & 7) * 4;
                const int gr = rowBase + r;
                a_stf[it] = (gr < M)
                    ? *reinterpret_cast<const float4*>(Af + (size_t)gr * K + k0 + c4)
                    : make_float4(0.f, 0.f, 0.f, 0.f);
            }
        }
        #pragma unroll
        for (int it = 0; it < 2; it++) {
            const int idx = tid + it * 256;
            const int n  = idx >> 2;
            const int c8 = (idx & 3) * 8;
            b_st[it] = *reinterpret_cast<const uint4*>(
                BT + (size_t)(colBase + n) * K + k0 + c8);
        }
    };

    auto store_stage = [&](__half* As, __half* Bs) {
        if (A_HALF) {
            #pragma unroll
            for (int it = 0; it < 2; it++) {
                const int idx = tid + it * 256;
                const int r  = idx >> 2;
                const int c8 = (idx & 3) * 8;
                *reinterpret_cast<uint4*>(As + r * LDT + c8) = a_sth[it];
            }
        } else {
            #pragma unroll
            for (int it = 0; it < 4; it++) {
                const int idx = tid + it * 256;
                const int r  = idx >> 3;
                const int c4 = (idx & 7) * 4;
                const __half2 h01 = __floats2half2_rn(a_stf[it].x, a_stf[it].y);
                const __half2 h23 = __floats2half2_rn(a_stf[it].z, a_stf[it].w);
                uint2 u;
                u.x = *reinterpret_cast<const uint32_t*>(&h01);
                u.y = *reinterpret_cast<const uint32_t*>(&h23);
                *reinterpret_cast<uint2*>(As + r * LDT + c4) = u;
            }
        }
        #pragma unroll
        for (int it = 0; it < 2; it++) {
            const int idx = tid + it * 256;
            const int n  = idx >> 2;
            const int c8 = (idx & 3) * 8;
            *reinterpret_cast<uint4*>(Bs + n * LDT + c8) = b_st[it];
        }
    };

    float acc[4][4][4];
    #pragma unroll
    for (int i = 0; i < 4; i++)
        #pragma unroll
        for (int j = 0; j < 4; j++)
            #pragma unroll
            for (int c = 0; c < 4; c++) acc[i][j][c] = 0.0f;

    load_stage(0);

    const int ntiles = K / BK;
    for (int it = 0; it < ntiles; it++) {
        __half* As = smemh + (it & 1) * STAGE;
        __half* Bs = As + ASZ;

        store_stage(As, Bs);
        __syncthreads();
        if (it + 1 < ntiles) load_stage((it + 1) * BK);

        #pragma unroll
        for (int ks = 0; ks < 2; ks++) {           // two k=16 steps
            const int kk = ks * 16;
            uint32_t af[4][4], bf[4][2];
            #pragma unroll
            for (int i = 0; i < 4; i++) {
                const uint32_t addr = (uint32_t)__cvta_generic_to_shared(
                    &As[(wrow + i * 16 + a_r) * LDT + kk + a_c]);
                LDSM_X4(af[i][0], af[i][1], af[i][2], af[i][3], addr);
            }
            #pragma unroll
            for (int p = 0; p < 2; p++) {
                const uint32_t addr = (uint32_t)__cvta_generic_to_shared(
                    &Bs[(wcol + p * 16 + b_n) * LDT + kk + b_k]);
                LDSM_X4(bf[2 * p][0], bf[2 * p][1], bf[2 * p + 1][0], bf[2 * p + 1][1], addr);
            }
            #pragma unroll
            for (int i = 0; i < 4; i++)
                #pragma unroll
                for (int j = 0; j < 4; j++)
                    mma_16x8x16(acc[i][j], af[i], bf[j]);
        }
    }

    // ---- epilogue: optional dinv scale, convert to fp16 ----
    #pragma unroll
    for (int i = 0; i < 4; i++) {
        #pragma unroll
        for (int half = 0; half < 2; half++) {
            const int gr = rowBase + wrow + i * 16 + g + half * 8;
            if (gr < M) {
                const float d = SCALE_EPI ? g_dinv[gr] : 1.0f;
                __half* dst = C16 + (size_t)gr * N + colBase + wcol;
                #pragma unroll
                for (int j = 0; j < 4; j++) {
                    const __half2 hv = __floats2half2_rn(acc[i][j][half * 2] * d,
                                                         acc[i][j][half * 2 + 1] * d);
                    *reinterpret_cast<__half2*>(dst + j * 8 + 2 * t) = hv;
                }
            }
        }
    }
}

// -------- weight transpose+convert: W[K][N] fp32 -> WT[N][K] fp16 -----------
__global__ void transpose_w_kernel(const float* __restrict__ W,
                                   __half* __restrict__ WT,
                                   int K, int N) {
    __shared__ float tile[32][33];
    const int k0 = blockIdx.y * 32;
    const int n0 = blockIdx.x * 32;
    const int tx = threadIdx.x, ty = threadIdx.y;   // 32 x 8
    #pragma unroll
    for (int i = 0; i < 32; i += 8)
        tile[ty + i][tx] = W[(size_t)(k0 + ty + i) * N + n0 + tx];
    __syncthreads();
    #pragma unroll
    for (int i = 0; i < 32; i += 8)
        WT[(size_t)(n0 + ty + i) * K + k0 + tx] = __float2half_rn(tile[tx][ty + i]);
}

// ======================= graph-side kernels =================================
__global__ void detect_dtype_kernel(const unsigned int* __restrict__ w, int nwords) {
    __shared__ unsigned int s_or;
    if (threadIdx.x == 0) s_or = 0u;
    __syncthreads();
    unsigned int v = 0u;
    for (int i = 2 * threadIdx.x + 1; i < nwords; i += 2 * blockDim.x) v |= w[i];
    atomicOr(&s_or, v);
    __syncthreads();
    if (threadIdx.x == 0) g_is64 = (s_or == 0u) ? 1 : 0;
}

__device__ __forceinline__ long long edge_get(const void* p, long long i) {
    return g_is64 ? ((const long long*)p)[i] : (long long)((const int*)p)[i];
}

__global__ void init_indeg_kernel(int n) {
    int i = blockIdx.x * blockDim.x + threadIdx.x;
    if (i < n) g_indeg[i] = 0;
}

__global__ void indeg_kernel(const void* __restrict__ edges, int E) {
    int e = blockIdx.x * blockDim.x + threadIdx.x;
    if (e < E) atomicAdd(&g_indeg[(int)edge_get(edges, e)], 1);
}

__global__ void scanA_kernel(int n) {
    __shared__ int s[256];
    const int t = threadIdx.x;
    const int i = blockIdx.x * 256 + t;
    int v = 0;
    if (i < n) {
        v = g_indeg[i];
        g_dinv[i] = rsqrtf((float)(v + 1));
    }
    s[t] = v;
    __syncthreads();
    #pragma unroll
    for (int off = 1; off < 256; off <<= 1) {
        int x = (t >= off) ? s[t - off] : 0;
        __syncthreads();
        s[t] += x;
        __syncthreads();
    }
    if (i < n) g_off[i + 1] = s[t];
    if (t == 255) g_bsum[blockIdx.x] = s[255];
}

__global__ void scanB_kernel(int nb) {
    __shared__ int s[256];
    const int t = threadIdx.x;
    s[t] = (t < nb) ? g_bsum[t] : 0;
    __syncthreads();
    #pragma unroll
    for (int off = 1; off < 256; off <<= 1) {
        int x = (t >= off) ? s[t - off] : 0;
        __syncthreads();
        s[t] += x;
        __syncthreads();
    }
    if (t < nb) g_bsum[t] = s[t];
}

__global__ void scanC_kernel(int n) {
    int i = blockIdx.x * blockDim.x + threadIdx.x;
    if (i >= n) return;
    const int b = i >> 8;
    const int add = (b > 0) ? g_bsum[b - 1] : 0;
    const int fin = g_off[i + 1] + add;
    g_off[i + 1] = fin;
    if (i + 1 < n) g_cursor[i + 1] = fin;
    if (i == 0) { g_off[0] = 0; g_cursor[0] = 0; }
}

__global__ void fill_kernel(const void* __restrict__ edges, int E) {
    int e = blockIdx.x * blockDim.x + threadIdx.x;
    if (e >= E) return;
    const int r = (int)edge_get(edges, e);
    const int c = (int)edge_get(edges, (long long)E + e);
    const int slot = atomicAdd(&g_cursor[r], 1);
    g_elist[slot] = c;
}

// ---- gather aggregation: SPLIT warps per destination node ------------------
template <int F, int SPLIT, bool RELU, bool SCALE_NBR, bool OUT_HALF>
__global__ void gather_kernel(const __half* __restrict__ hf,
                              const float* __restrict__ bias,
                              void* __restrict__ outp,
                              int M) {
    const int wunit = (int)((blockIdx.x * blockDim.x + threadIdx.x) >> 5);
    const int lane = threadIdx.x & 31;
    const int node = wunit / SPLIT;
    const int part = wunit - node * SPLIT;
    if (node >= M) return;
    const int fofs = part * (F / SPLIT) + lane * 4;

    const float d = g_dinv[node];
    const float selfs = SCALE_NBR ? d : 1.0f;

    float acc[4];
    {
        const uint2 raw = __ldg(reinterpret_cast<const uint2*>(hf + (size_t)node * F + fofs));
        const __half2* hp = reinterpret_cast<const __half2*>(&raw);
        const float2 f0 = __half22float2(hp[0]);
        const float2 f1 = __half22float2(hp[1]);
        acc[0] = selfs * f0.x; acc[1] = selfs * f0.y;
        acc[2] = selfs * f1.x; acc[3] = selfs * f1.y;
    }

    const int beg = g_off[node];
    const int end = g_off[node + 1];
    for (int i = beg; i < end; i += 32) {
        const int   my  = (i + lane < end) ? g_elist[i + lane] : 0;
        const float myd = SCALE_NBR ? g_dinv[my] : 1.0f;
        const int cnt = min(32, end - i);
        #pragma unroll 4
        for (int j = 0; j < cnt; j++) {
            const int   c  = __shfl_sync(0xffffffffu, my,  j);
            const float dc = SCALE_NBR ? __shfl_sync(0xffffffffu, myd, j) : 1.0f;
            const uint2 raw = __ldg(reinterpret_cast<const uint2*>(hf + (size_t)c * F + fofs));
            const __half2* hp = reinterpret_cast<const __half2*>(&raw);
            const float2 f0 = __half22float2(hp[0]);
            const float2 f1 = __half22float2(hp[1]);
            if (SCALE_NBR) {
                acc[0] = fmaf(dc, f0.x, acc[0]); acc[1] = fmaf(dc, f0.y, acc[1]);
                acc[2] = fmaf(dc, f1.x, acc[2]); acc[3] = fmaf(dc, f1.y, acc[3]);
            } else {
                acc[0] += f0.x; acc[1] += f0.y;
                acc[2] += f1.x; acc[3] += f1.y;
            }
        }
    }

    const float4 bv = __ldg(reinterpret_cast<const float4*>(bias + fofs));
    float4 v;
    v.x = fmaf(d, acc[0], bv.x);
    v.y = fmaf(d, acc[1], bv.y);
    v.z = fmaf(d, acc[2], bv.z);
    v.w = fmaf(d, acc[3], bv.w);
    if (RELU) {
        v.x = fmaxf(v.x, 0.f); v.y = fmaxf(v.y, 0.f);
        v.z = fmaxf(v.z, 0.f); v.w = fmaxf(v.w, 0.f);
    }
    if (OUT_HALF) {
        const __half2 h01 = __floats2half2_rn(v.x, v.y);
        const __half2 h23 = __floats2half2_rn(v.z, v.w);
        uint2 u;
        u.x = *reinterpret_cast<const uint32_t*>(&h01);
        u.y = *reinterpret_cast<const uint32_t*>(&h23);
        *reinterpret_cast<uint2*>((__half*)outp + (size_t)node * F + fofs) = u;
    } else {
        *reinterpret_cast<float4*>((float*)outp + (size_t)node * F + fofs) = v;
    }
}

// -------- static side stream for CSR/GEMM1 overlap (created pre-capture) ----
static cudaStream_t g_s2 = nullptr;
static cudaEvent_t  g_evFork = nullptr, g_evJoin = nullptr;
static bool g_streams_ok = false;
namespace {
struct StreamInit {
    StreamInit() {
        g_streams_ok =
            cudaStreamCreateWithFlags(&g_s2, cudaStreamNonBlocking) == cudaSuccess &&
            cudaEventCreateWithFlags(&g_evFork, cudaEventDisableTiming) == cudaSuccess &&
            cudaEventCreateWithFlags(&g_evJoin, cudaEventDisableTiming) == cudaSuccess;
    }
} g_stream_init;
}

// ---------------------------------------------------------------
extern "C" void kernel_launch(void* const* d_in, const int* in_sizes, int n_in,
                              void* d_out, int out_size) {
    const float* x     = (const float*)d_in[0];
    const void*  edges = d_in[1];
    const float* W1    = (const float*)d_in[2];
    const float* b1    = (const float*)d_in[3];
    const float* W2    = (const float*)d_in[4];
    const float* b2    = (const float*)d_in[5];
    float* out = (float*)d_out;

    const int M = in_sizes[0] / F_IN;
    const int E = in_sizes[1] / 2;
    const int NB = (M + 255) / 256;

    __half* h1f  = nullptr;  cudaGetSymbolAddress((void**)&h1f,  g_h1f);
    __half* agg1 = nullptr;  cudaGetSymbolAddress((void**)&agg1, g_agg1);
    __half* h2f  = nullptr;  cudaGetSymbolAddress((void**)&h2f,  g_h2f);
    __half* w1t  = nullptr;  cudaGetSymbolAddress((void**)&w1t,  g_w1t);
    __half* w2t  = nullptr;  cudaGetSymbolAddress((void**)&w2t,  g_w2t);

    const dim3 grid1(F_HID / BN, (M + BM - 1) / BM);
    const dim3 grid2(F_OUT / BN, (M + BM - 1) / BM);
    const dim3 tblk(32, 8);
    const int eb = (E + 255) / 256;
    int nwords = 2 * E;
    if (nwords > 4096) nwords = 4096;

    if (g_streams_ok) {
        // side: detect -> CSR chain -> w2t transpose (all off the main path)
        cudaEventRecord(g_evFork, 0);
        cudaStreamWaitEvent(g_s2, g_evFork, 0);

        detect_dtype_kernel<<<1, 256, 0, g_s2>>>((const unsigned int*)edges, nwords);
        init_indeg_kernel<<<NB, 256, 0, g_s2>>>(M);
        indeg_kernel<<<eb, 256, 0, g_s2>>>(edges, E);
        scanA_kernel<<<NB, 256, 0, g_s2>>>(M);
        scanB_kernel<<<1, 256, 0, g_s2>>>(NB);
        scanC_kernel<<<NB, 256, 0, g_s2>>>(M);
        fill_kernel<<<eb, 256, 0, g_s2>>>(edges, E);
        transpose_w_kernel<<<dim3(F_OUT / 32, F_HID / 32), tblk, 0, g_s2>>>(W2, w2t, F_HID, F_OUT);
        cudaEventRecord(g_evJoin, g_s2);

        // main: w1t transpose -> GEMM1 (no dependency on detect/CSR)
        transpose_w_kernel<<<dim3(F_HID / 32, F_IN / 32), tblk>>>(W1, w1t, F_IN, F_HID);
        mma_gemm_fp16<false, false><<<grid1, 256, GEMM_SMEM>>>(x, w1t, h1f, M, F_HID, F_IN);

        cudaStreamWaitEvent(0, g_evJoin, 0);
    } else {
        detect_dtype_kernel<<<1, 256>>>((const unsigned int*)edges, nwords);
        init_indeg_kernel<<<NB, 256>>>(M);
        indeg_kernel<<<eb, 256>>>(edges, E);
        scanA_kernel<<<NB, 256>>>(M);
        scanB_kernel<<<1, 256>>>(NB);
        scanC_kernel<<<NB, 256>>>(M);
        fill_kernel<<<eb, 256>>>(edges, E);
        transpose_w_kernel<<<dim3(F_HID / 32, F_IN / 32), tblk>>>(W1, w1t, F_IN, F_HID);
        transpose_w_kernel<<<dim3(F_OUT / 32, F_HID / 32), tblk>>>(W2, w2t, F_HID, F_OUT);
        mma_gemm_fp16<false, false><<<grid1, 256, GEMM_SMEM>>>(x, w1t, h1f, M, F_HID, F_IN);
    }

    // gather1 (2 warps/node): agg1[r] = relu(dinv[r]*(dinv[r]*h1[r] + sum dinv[c]*h1[c]) + b1)
    {
        const long long warps = (long long)M * 2;
        gather_kernel<F_HID, 2, true, true, true>
            <<<(int)((warps * 32 + 255) / 256), 256>>>(h1f, b1, agg1, M);
    }

    // GEMM2: hs2 = (agg1 @ W2) * dinv[row]  (A fp16 direct)
    mma_gemm_fp16<true, true><<<grid2, 256, GEMM_SMEM>>>(agg1, w2t, h2f, M, F_OUT, F_HID);

    // gather2 (1 warp/node): out[r] = dinv[r]*(hs2[r] + sum hs2[c]) + b2
    {
        const long long warps = (long long)M;
        gather_kernel<F_OUT, 1, false, false, false>
            <<<(int)((warps * 32 + 255) / 256), 256>>>(h2f, b2, out, M);
    }
}

// round 11
// speedup vs baseline: 5.4941x; 1.0180x over previous
#include <cuda_runtime.h>
#include <cuda_fp16.h>
#include <cstdint>

// GCN: out2 = GCNagg(relu(GCNagg(x@W1) + b1) @ W2) + b2
// R11: CSR side chain collapsed 8->5 launches (fused prep kernel; single-
//      kernel scan with last-block middle-scan). GEMM/gather path = R10
//      (ldmatrix.x4 fp16 m16n8k16, double-buffered; warp-per-node gathers).

#define N_NODES 50000
#define F_IN    256
#define F_HID   256
#define F_OUT   128
#define MAX_E   320000

// -------- scratch (device globals; no allocations allowed) --------
__device__ __align__(16) __half g_h1f [(size_t)N_NODES * F_HID];  // x@W1 (raw fp16)
__device__ __align__(16) __half g_agg1[(size_t)N_NODES * F_HID];  // layer-2 input fp16
__device__ __align__(16) __half g_h2f [(size_t)N_NODES * F_OUT];  // (agg1@W2)*dinv fp16
__device__ __align__(16) __half g_w1t [(size_t)F_IN  * F_HID];    // W1^T fp16 [N][K]
__device__ __align__(16) __half g_w2t [(size_t)F_HID * F_OUT];    // W2^T fp16 [N][K]
__device__ float g_dinv  [N_NODES];
__device__ int   g_indeg [N_NODES];
__device__ int   g_off   [N_NODES + 1];
__device__ int   g_cursor[N_NODES];
__device__ int   g_bsum  [256];
__device__ int   g_bpre  [256];
__device__ int   g_scan_count;
__device__ int   g_scan_ready;
__device__ int   g_elist [MAX_E];
__device__ int   g_is64;

// ======================= fp16 warp-MMA GEMM (double-buffered) ===============
__device__ __forceinline__ void mma_16x8x16(float* c, const uint32_t* a, const uint32_t* b) {
    asm volatile(
        "mma.sync.aligned.m16n8k16.row.col.f32.f16.f16.f32 "
        "{%0,%1,%2,%3}, {%4,%5,%6,%7}, {%8,%9}, {%0,%1,%2,%3};"
        : "+f"(c[0]), "+f"(c[1]), "+f"(c[2]), "+f"(c[3])
        : "r"(a[0]), "r"(a[1]), "r"(a[2]), "r"(a[3]), "r"(b[0]), "r"(b[1]));
}

#define LDSM_X4(r0, r1, r2, r3, addr) \
    asm volatile("ldmatrix.sync.aligned.m8n8.x4.shared.b16 {%0,%1,%2,%3}, [%4];" \
                 : "=r"(r0), "=r"(r1), "=r"(r2), "=r"(r3) : "r"(addr))

static constexpr int BM = 128, BN = 128, BK = 32;
static constexpr int LDT = 40;                   // smem row stride in halves (80B)
static constexpr int ASZ = BM * LDT;
static constexpr int BSZ = BN * LDT;
static constexpr int STAGE = ASZ + BSZ;
static constexpr int GEMM_SMEM = 2 * STAGE * 2;  // ~40KB

template <bool A_HALF, bool SCALE_EPI>
__global__ __launch_bounds__(256)
void mma_gemm_fp16(const void* __restrict__ Aptr,
                   const __half* __restrict__ BT,   // [N][K] fp16
                   __half* __restrict__ C16,
                   int M, int N, int K) {
    extern __shared__ __half smemh[];

    const int tid  = threadIdx.x;
    const int wid  = tid >> 5;
    const int lane = tid & 31;
    const int g    = lane >> 2;
    const int t    = lane & 3;
    const int wrow = (wid >> 2) * 64;
    const int wcol = (wid & 3) * 32;
    const int rowBase = blockIdx.y * BM;
    const int colBase = blockIdx.x * BN;

    const int a_r = lane & 15;
    const int a_c = (lane >> 4) * 8;
    const int b_n = ((lane >> 4) << 3) + (lane & 7);
    const int b_k = ((lane >> 3) & 1) * 8;

    float4 a_stf[4];
    uint4  a_sth[2];
    uint4  b_st[2];

    auto load_stage = [&](int k0) {
        if (A_HALF) {
            const __half* Ah = (const __half*)Aptr;
            #pragma unroll
            for (int it = 0; it < 2; it++) {
                const int idx = tid + it * 256;
                const int r  = idx >> 2;
                const int c8 = (idx & 3) * 8;
                const int gr = rowBase + r;
                a_sth[it] = (gr < M)
                    ? *reinterpret_cast<const uint4*>(Ah + (size_t)gr * K + k0 + c8)
                    : make_uint4(0u, 0u, 0u, 0u);
            }
        } else {
            const float* Af = (const float*)Aptr;
            #pragma unroll
            for (int it = 0; it < 4; it++) {
                const int idx = tid + it * 256;
                const int r  = idx >> 3;
                const int c4 = (idx & 7) * 4;
                const int gr = rowBase + r;
                a_stf[it] = (gr < M)
                    ? *reinterpret_cast<const float4*>(Af + (size_t)gr * K + k0 + c4)
                    : make_float4(0.f, 0.f, 0.f, 0.f);
            }
        }
        #pragma unroll
        for (int it = 0; it < 2; it++) {
            const int idx = tid + it * 256;
            const int n  = idx >> 2;
            const int c8 = (idx & 3) * 8;
            b_st[it] = *reinterpret_cast<const uint4*>(
                BT + (size_t)(colBase + n) * K + k0 + c8);
        }
    };

    auto store_stage = [&](__half* As, __half* Bs) {
        if (A_HALF) {
            #pragma unroll
            for (int it = 0; it < 2; it++) {
                const int idx = tid + it * 256;
                const int r  = idx >> 2;
                const int c8 = (idx & 3) * 8;
                *reinterpret_cast<uint4*>(As + r * LDT + c8) = a_sth[it];
            }
        } else {
            #pragma unroll
            for (int it = 0; it < 4; it++) {
                const int idx = tid + it * 256;
                const int r  = idx >> 3;
                const int c4 = (idx & 7) * 4;
                const __half2 h01 = __floats2half2_rn(a_stf[it].x, a_stf[it].y);
                const __half2 h23 = __floats2half2_rn(a_stf[it].z, a_stf[it].w);
                uint2 u;
                u.x = *reinterpret_cast<const uint32_t*>(&h01);
                u.y = *reinterpret_cast<const uint32_t*>(&h23);
                *reinterpret_cast<uint2*>(As + r * LDT + c4) = u;
            }
        }
        #pragma unroll
        for (int it = 0; it < 2; it++) {
            const int idx = tid + it * 256;
            const int n  = idx >> 2;
            const int c8 = (idx & 3) * 8;
            *reinterpret_cast<uint4*>(Bs + n * LDT + c8) = b_st[it];
        }
    };

    float acc[4][4][4];
    #pragma unroll
    for (int i = 0; i < 4; i++)
        #pragma unroll
        for (int j = 0; j < 4; j++)
            #pragma unroll
            for (int c = 0; c < 4; c++) acc[i][j][c] = 0.0f;

    load_stage(0);

    const int ntiles = K / BK;
    for (int it = 0; it < ntiles; it++) {
        __half* As = smemh + (it & 1) * STAGE;
        __half* Bs = As + ASZ;

        store_stage(As, Bs);
        __syncthreads();
        if (it + 1 < ntiles) load_stage((it + 1) * BK);

        #pragma unroll
        for (int ks = 0; ks < 2; ks++) {
            const int kk = ks * 16;
            uint32_t af[4][4], bf[4][2];
            #pragma unroll
            for (int i = 0; i < 4; i++) {
                const uint32_t addr = (uint32_t)__cvta_generic_to_shared(
                    &As[(wrow + i * 16 + a_r) * LDT + kk + a_c]);
                LDSM_X4(af[i][0], af[i][1], af[i][2], af[i][3], addr);
            }
            #pragma unroll
            for (int p = 0; p < 2; p++) {
                const uint32_t addr = (uint32_t)__cvta_generic_to_shared(
                    &Bs[(wcol + p * 16 + b_n) * LDT + kk + b_k]);
                LDSM_X4(bf[2 * p][0], bf[2 * p][1], bf[2 * p + 1][0], bf[2 * p + 1][1], addr);
            }
            #pragma unroll
            for (int i = 0; i < 4; i++)
                #pragma unroll
                for (int j = 0; j < 4; j++)
                    mma_16x8x16(acc[i][j], af[i], bf[j]);
        }
    }

    #pragma unroll
    for (int i = 0; i < 4; i++) {
        #pragma unroll
        for (int half = 0; half < 2; half++) {
            const int gr = rowBase + wrow + i * 16 + g + half * 8;
            if (gr < M) {
                const float d = SCALE_EPI ? g_dinv[gr] : 1.0f;
                __half* dst = C16 + (size_t)gr * N + colBase + wcol;
                #pragma unroll
                for (int j = 0; j < 4; j++) {
                    const __half2 hv = __floats2half2_rn(acc[i][j][half * 2] * d,
                                                         acc[i][j][half * 2 + 1] * d);
                    *reinterpret_cast<__half2*>(dst + j * 8 + 2 * t) = hv;
                }
            }
        }
    }
}

// -------- weight transpose+convert: W[K][N] fp32 -> WT[N][K] fp16 -----------
__global__ void transpose_w_kernel(const float* __restrict__ W,
                                   __half* __restrict__ WT,
                                   int K, int N) {
    __shared__ float tile[32][33];
    const int k0 = blockIdx.y * 32;
    const int n0 = blockIdx.x * 32;
    const int tx = threadIdx.x, ty = threadIdx.y;   // 32 x 8
    #pragma unroll
    for (int i = 0; i < 32; i += 8)
        tile[ty + i][tx] = W[(size_t)(k0 + ty + i) * N + n0 + tx];
    __syncthreads();
    #pragma unroll
    for (int i = 0; i < 32; i += 8)
        WT[(size_t)(n0 + ty + i) * K + k0 + tx] = __float2half_rn(tile[tx][ty + i]);
}

// ======================= graph-side kernels =================================
__device__ __forceinline__ long long edge_get(const void* p, long long i) {
    return g_is64 ? ((const long long*)p)[i] : (long long)((const int*)p)[i];
}

// prep: blocks [0, NB) zero g_indeg; block NB does dtype detection + flag reset
__global__ void prep_kernel(const unsigned int* __restrict__ w, int nwords, int n) {
    if ((int)blockIdx.x == (int)gridDim.x - 1) {
        __shared__ unsigned int s_or;
        if (threadIdx.x == 0) {
            s_or = 0u;
            g_scan_count = 0;
            g_scan_ready = 0;
        }
        __syncthreads();
        unsigned int v = 0u;
        for (int i = 2 * threadIdx.x + 1; i < nwords; i += 2 * blockDim.x) v |= w[i];
        atomicOr(&s_or, v);
        __syncthreads();
        if (threadIdx.x == 0) g_is64 = (s_or == 0u) ? 1 : 0;
        return;
    }
    const int i = blockIdx.x * blockDim.x + threadIdx.x;
    if (i < n) g_indeg[i] = 0;
}

__global__ void indeg_kernel(const void* __restrict__ edges, int E) {
    int e = blockIdx.x * blockDim.x + threadIdx.x;
    if (e < E) atomicAdd(&g_indeg[(int)edge_get(edges, e)], 1);
}

// single-kernel scan: local scan + last-arriving block scans the block sums.
// All nb (<=256) blocks are co-resident (nb*256 <= 50176 threads) -> no deadlock.
__global__ void scan_fused_kernel(int n, int nb) {
    __shared__ int s[256];
    __shared__ int s_prev;
    __shared__ int s_islast;
    const int t = threadIdx.x;
    const int bid = blockIdx.x;
    const int i = bid * 256 + t;

    int v = 0;
    if (i < n) {
        v = g_indeg[i];
        g_dinv[i] = rsqrtf((float)(v + 1));
    }
    s[t] = v;
    __syncthreads();
    #pragma unroll
    for (int off = 1; off < 256; off <<= 1) {
        int x = (t >= off) ? s[t - off] : 0;
        __syncthreads();
        s[t] += x;
        __syncthreads();
    }
    const int incl  = s[t];
    const int total = s[255];

    if (t == 0) {
        g_bsum[bid] = total;
        __threadfence();
        const int done = atomicAdd(&g_scan_count, 1);
        s_islast = (done == nb - 1) ? 1 : 0;
    }
    __syncthreads();

    if (s_islast) {
        // this block is the last to arrive: all other block sums are visible
        int bv = (t < nb) ? g_bsum[t] : 0;
        s[t] = bv;
        __syncthreads();
        #pragma unroll
        for (int off = 1; off < 256; off <<= 1) {
            int x = (t >= off) ? s[t - off] : 0;
            __syncthreads();
            s[t] += x;
            __syncthreads();
        }
        if (t < nb) g_bpre[t] = s[t] - bv;   // exclusive prefix
        __threadfence();
        __syncthreads();
        if (t == 0) atomicExch(&g_scan_ready, 1);
    }

    if (t == 0) {
        while (atomicAdd(&g_scan_ready, 0) == 0) {}
        __threadfence();
        s_prev = g_bpre[bid];
    }
    __syncthreads();

    if (i < n) {
        const int fin = incl + s_prev;
        g_off[i + 1] = fin;
        if (i + 1 < n) g_cursor[i + 1] = fin;
        if (i == 0) { g_off[0] = 0; g_cursor[0] = 0; }
    }
}

__global__ void fill_kernel(const void* __restrict__ edges, int E) {
    int e = blockIdx.x * blockDim.x + threadIdx.x;
    if (e >= E) return;
    const int r = (int)edge_get(edges, e);
    const int c = (int)edge_get(edges, (long long)E + e);
    const int slot = atomicAdd(&g_cursor[r], 1);
    g_elist[slot] = c;
}

// ---- gather aggregation: SPLIT warps per destination node ------------------
template <int F, int SPLIT, bool RELU, bool SCALE_NBR, bool OUT_HALF>
__global__ void gather_kernel(const __half* __restrict__ hf,
                              const float* __restrict__ bias,
                              void* __restrict__ outp,
                              int M) {
    const int wunit = (int)((blockIdx.x * blockDim.x + threadIdx.x) >> 5);
    const int lane = threadIdx.x & 31;
    const int node = wunit / SPLIT;
    const int part = wunit - node * SPLIT;
    if (node >= M) return;
    const int fofs = part * (F / SPLIT) + lane * 4;

    const float d = g_dinv[node];
    const float selfs = SCALE_NBR ? d : 1.0f;

    float acc[4];
    {
        const uint2 raw = __ldg(reinterpret_cast<const uint2*>(hf + (size_t)node * F + fofs));
        const __half2* hp = reinterpret_cast<const __half2*>(&raw);
        const float2 f0 = __half22float2(hp[0]);
        const float2 f1 = __half22float2(hp[1]);
        acc[0] = selfs * f0.x; acc[1] = selfs * f0.y;
        acc[2] = selfs * f1.x; acc[3] = selfs * f1.y;
    }

    const int beg = g_off[node];
    const int end = g_off[node + 1];
    for (int i = beg; i < end; i += 32) {
        const int   my  = (i + lane < end) ? g_elist[i + lane] : 0;
        const float myd = SCALE_NBR ? g_dinv[my] : 1.0f;
        const int cnt = min(32, end - i);
        #pragma unroll 4
        for (int j = 0; j < cnt; j++) {
            const int   c  = __shfl_sync(0xffffffffu, my,  j);
            const float dc = SCALE_NBR ? __shfl_sync(0xffffffffu, myd, j) : 1.0f;
            const uint2 raw = __ldg(reinterpret_cast<const uint2*>(hf + (size_t)c * F + fofs));
            const __half2* hp = reinterpret_cast<const __half2*>(&raw);
            const float2 f0 = __half22float2(hp[0]);
            const float2 f1 = __half22float2(hp[1]);
            if (SCALE_NBR) {
                acc[0] = fmaf(dc, f0.x, acc[0]); acc[1] = fmaf(dc, f0.y, acc[1]);
                acc[2] = fmaf(dc, f1.x, acc[2]); acc[3] = fmaf(dc, f1.y, acc[3]);
            } else {
                acc[0] += f0.x; acc[1] += f0.y;
                acc[2] += f1.x; acc[3] += f1.y;
            }
        }
    }

    const float4 bv = __ldg(reinterpret_cast<const float4*>(bias + fofs));
    float4 v;
    v.x = fmaf(d, acc[0], bv.x);
    v.y = fmaf(d, acc[1], bv.y);
    v.z = fmaf(d, acc[2], bv.z);
    v.w = fmaf(d, acc[3], bv.w);
    if (RELU) {
        v.x = fmaxf(v.x, 0.f); v.y = fmaxf(v.y, 0.f);
        v.z = fmaxf(v.z, 0.f); v.w = fmaxf(v.w, 0.f);
    }
    if (OUT_HALF) {
        const __half2 h01 = __floats2half2_rn(v.x, v.y);
        const __half2 h23 = __floats2half2_rn(v.z, v.w);
        uint2 u;
        u.x = *reinterpret_cast<const uint32_t*>(&h01);
        u.y = *reinterpret_cast<const uint32_t*>(&h23);
        *reinterpret_cast<uint2*>((__half*)outp + (size_t)node * F + fofs) = u;
    } else {
        *reinterpret_cast<float4*>((float*)outp + (size_t)node * F + fofs) = v;
    }
}

// -------- static side stream for CSR/GEMM1 overlap (created pre-capture) ----
static cudaStream_t g_s2 = nullptr;
static cudaEvent_t  g_evFork = nullptr, g_evJoin = nullptr;
static bool g_streams_ok = false;
namespace {
struct StreamInit {
    StreamInit() {
        g_streams_ok =
            cudaStreamCreateWithFlags(&g_s2, cudaStreamNonBlocking) == cudaSuccess &&
            cudaEventCreateWithFlags(&g_evFork, cudaEventDisableTiming) == cudaSuccess &&
            cudaEventCreateWithFlags(&g_evJoin, cudaEventDisableTiming) == cudaSuccess;
    }
} g_stream_init;
}

// ---------------------------------------------------------------
extern "C" void kernel_launch(void* const* d_in, const int* in_sizes, int n_in,
                              void* d_out, int out_size) {
    const float* x     = (const float*)d_in[0];
    const void*  edges = d_in[1];
    const float* W1    = (const float*)d_in[2];
    const float* b1    = (const float*)d_in[3];
    const float* W2    = (const float*)d_in[4];
    const float* b2    = (const float*)d_in[5];
    float* out = (float*)d_out;

    const int M = in_sizes[0] / F_IN;
    const int E = in_sizes[1] / 2;
    const int NB = (M + 255) / 256;

    __half* h1f  = nullptr;  cudaGetSymbolAddress((void**)&h1f,  g_h1f);
    __half* agg1 = nullptr;  cudaGetSymbolAddress((void**)&agg1, g_agg1);
    __half* h2f  = nullptr;  cudaGetSymbolAddress((void**)&h2f,  g_h2f);
    __half* w1t  = nullptr;  cudaGetSymbolAddress((void**)&w1t,  g_w1t);
    __half* w2t  = nullptr;  cudaGetSymbolAddress((void**)&w2t,  g_w2t);

    const dim3 grid1(F_HID / BN, (M + BM - 1) / BM);
    const dim3 grid2(F_OUT / BN, (M + BM - 1) / BM);
    const dim3 tblk(32, 8);
    const int eb = (E + 255) / 256;
    int nwords = 2 * E;
    if (nwords > 4096) nwords = 4096;

    if (g_streams_ok) {
        // side: prep (detect+zero+flags) -> indeg -> fused scan -> fill -> w2t
        cudaEventRecord(g_evFork, 0);
        cudaStreamWaitEvent(g_s2, g_evFork, 0);

        prep_kernel<<<NB + 1, 256, 0, g_s2>>>((const unsigned int*)edges, nwords, M);
        indeg_kernel<<<eb, 256, 0, g_s2>>>(edges, E);
        scan_fused_kernel<<<NB, 256, 0, g_s2>>>(M, NB);
        fill_kernel<<<eb, 256, 0, g_s2>>>(edges, E);
        transpose_w_kernel<<<dim3(F_OUT / 32, F_HID / 32), tblk, 0, g_s2>>>(W2, w2t, F_HID, F_OUT);
        cudaEventRecord(g_evJoin, g_s2);

        // main: w1t transpose -> GEMM1 (no dependency on detect/CSR)
        transpose_w_kernel<<<dim3(F_HID / 32, F_IN / 32), tblk>>>(W1, w1t, F_IN, F_HID);
        mma_gemm_fp16<false, false><<<grid1, 256, GEMM_SMEM>>>(x, w1t, h1f, M, F_HID, F_IN);

        cudaStreamWaitEvent(0, g_evJoin, 0);
    } else {
        prep_kernel<<<NB + 1, 256>>>((const unsigned int*)edges, nwords, M);
        indeg_kernel<<<eb, 256>>>(edges, E);
        scan_fused_kernel<<<NB, 256>>>(M, NB);
        fill_kernel<<<eb, 256>>>(edges, E);
        transpose_w_kernel<<<dim3(F_HID / 32, F_IN / 32), tblk>>>(W1, w1t, F_IN, F_HID);
        transpose_w_kernel<<<dim3(F_OUT / 32, F_HID / 32), tblk>>>(W2, w2t, F_HID, F_OUT);
        mma_gemm_fp16<false, false><<<grid1, 256, GEMM_SMEM>>>(x, w1t, h1f, M, F_HID, F_IN);
    }

    // gather1 (2 warps/node): agg1[r] = relu(dinv[r]*(dinv[r]*h1[r] + sum dinv[c]*h1[c]) + b1)
    {
        const long long warps = (long long)M * 2;
        gather_kernel<F_HID, 2, true, true, true>
            <<<(int)((warps * 32 + 255) / 256), 256>>>(h1f, b1, agg1, M);
    }

    // GEMM2: hs2 = (agg1 @ W2) * dinv[row]  (A fp16 direct)
    mma_gemm_fp16<true, true><<<grid2, 256, GEMM_SMEM>>>(agg1, w2t, h2f, M, F_OUT, F_HID);

    // gather2 (1 warp/node): out[r] = dinv[r]*(hs2[r] + sum hs2[c]) + b2
    {
        const long long warps = (long long)M;
        gather_kernel<F_OUT, 1, false, false, false>
            <<<(int)((warps * 32 + 255) / 256), 256>>>(h2f, b2, out, M);
    }
}